// round 13
// baseline (speedup 1.0000x reference)
#include <cuda_runtime.h>
#include <cuda_fp16.h>
#include <math.h>
#include <stdint.h>

// ---------------- problem dims ----------------
#define BSZ    2
#define TLEN   2048
#define DM     1024
#define NST    16
#define DTRANK 64
#define SSMW   96
#define MTOT   (BSZ*TLEN)     // 4096
#define NCHNK  64
#define CLEN   (TLEN/NCHNK)   // 32
#define TCH    128
#define TLCH   (TLEN/TCH)     // 16
#define XPK    4              // x_proj split-K slices

// ---------------- device scratch (no allocations) ----------------
__device__ __half g_xinh[(size_t)MTOT * DM];
__device__ __half g_gateh[(size_t)MTOT * DM];
__device__ __half g_xch [(size_t)MTOT * DM];
__device__ float g_ssm  [(size_t)MTOT * SSMW];
__device__ float g_part [(size_t)XPK * MTOT * SSMW];
__device__ __half g_dth [(size_t)MTOT * DTRANK];
__device__ float g_delta[(size_t)MTOT * DM];
__device__ float g_sp   [(size_t)BSZ * NCHNK * DM];
__device__ float g_hend [(size_t)BSZ * NCHNK * NST * DM];
__device__ float g_hinit[(size_t)BSZ * NCHNK * NST * DM];
__device__ __half g_A2h [(size_t)MTOT * 2 * DM];   // [y | x]
__device__ __half g_Binh[(size_t)2 * DM * DM];
__device__ __half g_Bxph[(size_t)SSMW * DM];
__device__ __half g_Bdth[(size_t)DM * DTRANK];
__device__ __half g_B2h [(size_t)DM * 2 * DM];     // row n: [Wout_n | Wskip_n]

// ---------------- helpers ----------------
__device__ __forceinline__ uint32_t smem_u32(const void* p) {
    uint32_t a;
    asm("{ .reg .u64 t; cvta.to.shared.u64 t, %1; cvt.u32.u64 %0, t; }" : "=r"(a) : "l"(p));
    return a;
}
#define SW128(o) ((o) ^ (((o) >> 3) & 0x70))

__device__ __forceinline__ void ldm_x4(uint32_t* r, uint32_t addr) {
    asm volatile("ldmatrix.sync.aligned.m8n8.x4.shared.b16 {%0,%1,%2,%3}, [%4];"
                 : "=r"(r[0]), "=r"(r[1]), "=r"(r[2]), "=r"(r[3]) : "r"(addr));
}
__device__ __forceinline__ void mma_f16(float* d, const uint32_t* a, const uint32_t* b) {
    asm volatile("mma.sync.aligned.m16n8k16.row.col.f32.f16.f16.f32 "
                 "{%0,%1,%2,%3}, {%4,%5,%6,%7}, {%8,%9}, {%0,%1,%2,%3};"
                 : "+f"(d[0]), "+f"(d[1]), "+f"(d[2]), "+f"(d[3])
                 : "r"(a[0]), "r"(a[1]), "r"(a[2]), "r"(a[3]), "r"(b[0]), "r"(b[1]));
}
__device__ __forceinline__ uint32_t pack2h(float a, float b) {
    __half2 h = __floats2half2_rn(a, b);
    return *(uint32_t*)&h;
}
__device__ __forceinline__ float softplus_f(float v) {
    return (v > 20.f) ? v : __logf(1.f + __expf(v));
}
__device__ __forceinline__ float silu_f(float v) {
    return v / (1.f + __expf(-v));
}

// ---------------- HMMA fp16 GEMM ----------------
// MODE 0: C = acc + bias (+ bias2)      (out+skip fused)
// MODE 2: delta = softplus(acc+bias)    (dt_proj)
// MODE 4: in_proj: x_in -> g_xinh ; res -> silu -> g_gateh
// MODE 5: x_proj split-K partial
template<int MODE, int BM>
__global__ void __launch_bounds__(256, 2)
gemm_mma(const __half* __restrict__ A, int lda,
         const __half* __restrict__ B, int ldb,
         int Ntot, int KT,
         const float* __restrict__ bias, const float* __restrict__ bias2,
         float* __restrict__ C, int ldc,
         __half* __restrict__ dth)
{
    constexpr int ABYTES = BM * 128;
    constexpr int STG    = ABYTES + 16384;
    constexpr int NT     = (BM == 128) ? 8 : 4;
    constexpr int STAGES = (BM == 128) ? 3 : 4;

    extern __shared__ char smem[];
    const uint32_t sb  = smem_u32(smem);
    const int tid  = threadIdx.x;
    const int wid  = tid >> 5;
    const int lane = tid & 31;
    const int bm   = blockIdx.y * BM;
    const int bn   = blockIdx.x * 128;
    const int kbase = (MODE == 5) ? blockIdx.z * KT * 64 : 0;
    const int wrow = (BM == 128) ? (wid & 3) * 32 : (wid & 1) * 32;
    const int wcol = (BM == 128) ? (wid >> 2) * 64 : (wid >> 1) * 32;

    float acc[2][NT][4];
#pragma unroll
    for (int m = 0; m < 2; m++)
#pragma unroll
        for (int n = 0; n < NT; n++)
#pragma unroll
            for (int v = 0; v < 4; v++) acc[m][n][v] = 0.f;

    auto load_stage = [&](int kt, int s) {
        uint32_t stg = sb + s * STG;
        int koff = kbase + kt * 64;
#pragma unroll
        for (int i = 0; i < BM / 32; i++) {
            int chunk = tid + i * 256;
            int row = chunk >> 3, c16 = chunk & 7;
            uint32_t dst = stg + SW128(row * 128 + c16 * 16);
            const __half* src = A + (size_t)(bm + row) * lda + koff + c16 * 8;
            asm volatile("cp.async.cg.shared.global [%0], [%1], 16;"
                         :: "r"(dst), "l"(src) : "memory");
        }
#pragma unroll
        for (int i = 0; i < 4; i++) {
            int chunk = tid + i * 256;
            int row = chunk >> 3, c16 = chunk & 7;
            uint32_t dst = stg + ABYTES + SW128(row * 128 + c16 * 16);
            int gr = bn + row;
            int sz = 16;
            if (gr >= Ntot) { gr = 0; sz = 0; }
            const __half* src = B + (size_t)gr * ldb + koff + c16 * 8;
            asm volatile("cp.async.cg.shared.global [%0], [%1], 16, %2;"
                         :: "r"(dst), "l"(src), "r"(sz) : "memory");
        }
        asm volatile("cp.async.commit_group;" ::: "memory");
    };

    const int g = lane >> 3, r = lane & 7;
    const uint32_t aoff0 = (wrow + (g & 1) * 8 + r) * 128 + (g >> 1) * 16;
    const uint32_t boff0 = (wcol + (g >> 1) * 8 + r) * 128 + (g & 1) * 16;

    uint32_t afr[2][2][4];
    uint32_t bfr[2][NT][2];

    auto ld_frags = [&](uint32_t stg, int ks, int buf) {
        const int kByte = ks * 32;
#pragma unroll
        for (int m = 0; m < 2; m++)
            ldm_x4(afr[buf][m], stg + SW128(aoff0 + m * 16 * 128 + kByte));
#pragma unroll
        for (int nb = 0; nb < NT / 2; nb++) {
            uint32_t t[4];
            ldm_x4(t, stg + ABYTES + SW128(boff0 + nb * 16 * 128 + kByte));
            bfr[buf][nb * 2][0] = t[0]; bfr[buf][nb * 2][1] = t[1];
            bfr[buf][nb * 2 + 1][0] = t[2]; bfr[buf][nb * 2 + 1][1] = t[3];
        }
    };
    auto do_mma = [&](int buf) {
#pragma unroll
        for (int m = 0; m < 2; m++)
#pragma unroll
            for (int n = 0; n < NT; n++)
                mma_f16(acc[m][n], afr[buf][m], bfr[buf][n]);
    };

    int pf = KT < (STAGES - 1) ? KT : (STAGES - 1);
    for (int s = 0; s < pf; s++) load_stage(s, s);

    for (int kt = 0; kt < KT; kt++) {
        int w = KT - kt - 1;
        if (w > STAGES - 2) w = STAGES - 2;
        if (w == 0)      asm volatile("cp.async.wait_group 0;" ::: "memory");
        else if (w == 1) asm volatile("cp.async.wait_group 1;" ::: "memory");
        else             asm volatile("cp.async.wait_group 2;" ::: "memory");
        __syncthreads();
        if (kt + STAGES - 1 < KT) load_stage(kt + STAGES - 1, (kt + STAGES - 1) % STAGES);

        uint32_t stg = sb + (kt % STAGES) * STG;
        ld_frags(stg, 0, 0);
#pragma unroll
        for (int ks = 0; ks < 4; ks++) {
            int cur = ks & 1;
            if (ks < 3) ld_frags(stg, ks + 1, cur ^ 1);
            do_mma(cur);
        }
    }
    __syncthreads();

    float* epi = (float*)smem;
#pragma unroll
    for (int m = 0; m < 2; m++)
#pragma unroll
        for (int n = 0; n < NT; n++) {
            int row = wrow + m * 16 + (lane >> 2);
            int col = wcol + n * 8 + (lane & 3) * 2;
            epi[row * 128 + col]           = acc[m][n][0];
            epi[row * 128 + col + 1]       = acc[m][n][1];
            epi[(row + 8) * 128 + col]     = acc[m][n][2];
            epi[(row + 8) * 128 + col + 1] = acc[m][n][3];
        }
    __syncthreads();

    const float4* epi4 = (const float4*)epi;
    constexpr int EIT = BM / 8;
    if (MODE == 0) {
#pragma unroll 4
        for (int i = 0; i < EIT; i++) {
            int e = tid + i * 256;
            int row = e >> 5, c4 = e & 31;
            float4 v = epi4[e];
            int n = bn + c4 * 4;
            v.x += bias[n + 0]; v.y += bias[n + 1]; v.z += bias[n + 2]; v.w += bias[n + 3];
            if (bias2) {
                v.x += bias2[n + 0]; v.y += bias2[n + 1]; v.z += bias2[n + 2]; v.w += bias2[n + 3];
            }
            *(float4*)(C + (size_t)(bm + row) * ldc + n) = v;
        }
    } else if (MODE == 4) {
#pragma unroll 4
        for (int i = 0; i < EIT; i++) {
            int e = tid + i * 256;
            int row = e >> 5, c4 = e & 31;
            float4 v = epi4[e];
            int n = bn + c4 * 4;
            v.x += bias[n + 0]; v.y += bias[n + 1]; v.z += bias[n + 2]; v.w += bias[n + 3];
            if (bn < DM) {
                uint2 pk = make_uint2(pack2h(v.x, v.y), pack2h(v.z, v.w));
                *(uint2*)(g_xinh + (size_t)(bm + row) * DM + n) = pk;
            } else {
                uint2 pk = make_uint2(pack2h(silu_f(v.x), silu_f(v.y)),
                                      pack2h(silu_f(v.z), silu_f(v.w)));
                *(uint2*)(g_gateh + (size_t)(bm + row) * DM + (n - DM)) = pk;
            }
        }
    } else if (MODE == 2) {
#pragma unroll 4
        for (int i = 0; i < EIT; i++) {
            int e = tid + i * 256;
            int row = e >> 5, c4 = e & 31;
            float4 v = epi4[e];
            int n = bn + c4 * 4;
            v.x += bias[n + 0]; v.y += bias[n + 1]; v.z += bias[n + 2]; v.w += bias[n + 3];
            float4 sp;
            sp.x = softplus_f(v.x);
            sp.y = softplus_f(v.y);
            sp.z = softplus_f(v.z);
            sp.w = softplus_f(v.w);
            *(float4*)(C + (size_t)(bm + row) * DM + n) = sp;
        }
    } else { // MODE 5
        float* part = C + (size_t)blockIdx.z * MTOT * SSMW;
        for (int i = 0; i < EIT; i++) {
            int e = tid + i * 256;
            int row = e >> 5, c4 = e & 31;
            if (c4 >= 24) continue;
            float4 v = epi4[e];
            *(float4*)(part + (size_t)(bm + row) * SSMW + c4 * 4) = v;
        }
    }
}

#define GSMEM128 (3 * (128 * 128 + 16384))   // 98304
#define GSMEM64  (4 * (64 * 128 + 16384))    // 98304

// ---------------- x_proj split-K reduce (float4) ----------------
__global__ void xp_reduce(const float* __restrict__ xproj_b)
{
    int i4 = blockIdx.x * 256 + threadIdx.x;
    if (i4 >= MTOT * SSMW / 4) return;
    int i = i4 * 4;
    int m = i / SSMW, c = i % SSMW;
    float4 s = *(const float4*)(xproj_b + c);
#pragma unroll
    for (int z = 0; z < XPK; z++) {
        float4 p = *(const float4*)(g_part + (size_t)z * MTOT * SSMW + i);
        s.x += p.x; s.y += p.y; s.z += p.z; s.w += p.w;
    }
    *(float4*)(g_ssm + i) = s;
    if (c < DTRANK) {
        uint2 pk = make_uint2(pack2h(s.x, s.y), pack2h(s.z, s.w));
        *(uint2*)(g_dth + (size_t)m * DTRANK + c) = pk;
    }
}

// ---------------- fused converts (float4 vectorized) ----------------
__global__ void prep_all(const float* __restrict__ x, const float* __restrict__ in_w,
                         const float* __restrict__ xproj_w, const float* __restrict__ dt_w,
                         const float* __restrict__ out_w, const float* __restrict__ skip_w)
{
    const int NX  = MTOT * DM / 4;
    const int NIN = 2 * DM * DM / 4;
    const int NXP = SSMW * DM / 4;
    const int NDT = DM * DTRANK / 4;
    const int NO  = DM * DM / 4;
    int i = blockIdx.x * 256 + threadIdx.x;
    if (i < NX) {
        int e = i * 4;
        int m = e >> 10, c = e & 1023;
        float4 v = *(const float4*)(x + e);
        *(uint2*)(g_A2h + (size_t)m * 2048 + 1024 + c) =
            make_uint2(pack2h(v.x, v.y), pack2h(v.z, v.w));
        return;
    }
    i -= NX;
    if (i < NIN) {
        float4 v = *(const float4*)(in_w + i * 4);
        *(uint2*)(g_Binh + i * 4) = make_uint2(pack2h(v.x, v.y), pack2h(v.z, v.w));
        return;
    }
    i -= NIN;
    if (i < NXP) {
        float4 v = *(const float4*)(xproj_w + i * 4);
        *(uint2*)(g_Bxph + i * 4) = make_uint2(pack2h(v.x, v.y), pack2h(v.z, v.w));
        return;
    }
    i -= NXP;
    if (i < NDT) {
        float4 v = *(const float4*)(dt_w + i * 4);
        *(uint2*)(g_Bdth + i * 4) = make_uint2(pack2h(v.x, v.y), pack2h(v.z, v.w));
        return;
    }
    i -= NDT;
    if (i < NO) {
        int e = i * 4;
        int m = e >> 10, c = e & 1023;
        size_t o = (size_t)m * 2048;
        float4 v = *(const float4*)(out_w + e);
        *(uint2*)(g_B2h + o + c) = make_uint2(pack2h(v.x, v.y), pack2h(v.z, v.w));
        v = *(const float4*)(skip_w + e);
        *(uint2*)(g_B2h + o + 1024 + c) = make_uint2(pack2h(v.x, v.y), pack2h(v.z, v.w));
    }
}

// ---------------- depthwise causal conv (k=4) + silu, 4 channels/thread -----
__global__ void conv_silu(const float* __restrict__ cw, const float* __restrict__ cb)
{
    int gid = blockIdx.x * blockDim.x + threadIdx.x;
    if (gid >= BSZ * (DM / 4) * TCH) return;
    int d4 = gid % (DM / 4);
    int r  = gid / (DM / 4);
    int tc = r % TCH;
    int b  = r / TCH;
    int d  = d4 * 4;

    float w[4][4], bs[4];
#pragma unroll
    for (int j = 0; j < 4; j++) {
        float4 wv = *(const float4*)(cw + (d + j) * 4);
        w[j][0] = wv.x; w[j][1] = wv.y; w[j][2] = wv.z; w[j][3] = wv.w;
        bs[j] = cb[d + j];
    }
    int t0 = tc * TLCH;

    const uint2* xin = (const uint2*)g_xinh + (size_t)b * TLEN * (DM / 4) + d4;
    uint2* xout = (uint2*)g_xch + (size_t)b * TLEN * (DM / 4) + d4;

    auto unpk = [](uint2 u, float* f) {
        __half2 lo = *(__half2*)&u.x, hi = *(__half2*)&u.y;
        float2 a = __half22float2(lo), c = __half22float2(hi);
        f[0] = a.x; f[1] = a.y; f[2] = c.x; f[3] = c.y;
    };

    float hist[3][4];
#pragma unroll
    for (int k = 0; k < 3; k++)
#pragma unroll
        for (int j = 0; j < 4; j++) hist[k][j] = 0.f;
    if (t0 - 3 >= 0) unpk(xin[(size_t)(t0 - 3) * (DM / 4)], hist[0]);
    if (t0 - 2 >= 0) unpk(xin[(size_t)(t0 - 2) * (DM / 4)], hist[1]);
    if (t0 - 1 >= 0) unpk(xin[(size_t)(t0 - 1) * (DM / 4)], hist[2]);

#pragma unroll 4
    for (int i = 0; i < TLCH; i++) {
        int t = t0 + i;
        float x0[4];
        unpk(xin[(size_t)t * (DM / 4)], x0);
        float s[4];
#pragma unroll
        for (int j = 0; j < 4; j++) {
            float a = bs[j];
            a = fmaf(w[j][0], hist[0][j], a);
            a = fmaf(w[j][1], hist[1][j], a);
            a = fmaf(w[j][2], hist[2][j], a);
            a = fmaf(w[j][3], x0[j], a);
            s[j] = silu_f(a);
        }
        xout[(size_t)t * (DM / 4)] = make_uint2(pack2h(s[0], s[1]), pack2h(s[2], s[3]));
#pragma unroll
        for (int j = 0; j < 4; j++) {
            hist[0][j] = hist[1][j]; hist[1][j] = hist[2][j]; hist[2][j] = x0[j];
        }
    }
}

// ---------------- dA powers ----------------
struct AConsts {
    float Ac[NST];
    float Ac0;
    bool  geom;
};
__device__ __forceinline__ AConsts load_aconsts(const float* A_log) {
    AConsts a;
#pragma unroll
    for (int n = 0; n < NST; n++) a.Ac[n] = -__expf(A_log[n]);
    a.Ac0 = a.Ac[0];
    a.geom = true;
#pragma unroll
    for (int n = 0; n < NST; n++)
        a.geom = a.geom && (fabsf(a.Ac[n] - (float)(n + 1) * a.Ac0) <= 1e-5f * fabsf(a.Ac[n]));
    return a;
}
__device__ __forceinline__ void da_powers(const AConsts& a, float de, float* pw) {
    if (a.geom) {
        float r = __expf(a.Ac0 * de);
        pw[0] = r;
        pw[1] = pw[0] * pw[0];  pw[2] = pw[1] * pw[0];  pw[3] = pw[1] * pw[1];
        pw[4] = pw[2] * pw[1];  pw[5] = pw[2] * pw[2];  pw[6] = pw[3] * pw[2];
        pw[7] = pw[3] * pw[3];  pw[8] = pw[4] * pw[3];  pw[9] = pw[4] * pw[4];
        pw[10] = pw[5] * pw[4]; pw[11] = pw[5] * pw[5]; pw[12] = pw[6] * pw[5];
        pw[13] = pw[6] * pw[6]; pw[14] = pw[7] * pw[6]; pw[15] = pw[7] * pw[7];
    } else {
#pragma unroll
        for (int n = 0; n < NST; n++) pw[n] = __expf(a.Ac[n] * de);
    }
}

// ---------------- chunked selective scan ----------------
__global__ void scan_passA(const float* __restrict__ A_log)
{
    int gid = blockIdx.x * blockDim.x + threadIdx.x;
    if (gid >= BSZ * NCHNK * DM) return;
    int d = gid % DM;
    int r = gid / DM;
    int c = r % NCHNK;
    int b = r / NCHNK;

    AConsts a = load_aconsts(A_log);
    float h[NST];
#pragma unroll
    for (int n = 0; n < NST; n++) h[n] = 0.f;
    float sp = 0.f;

    int m0 = b * TLEN + c * CLEN;
    float de = g_delta[(size_t)m0 * DM + d];
    float xc = __half2float(g_xch[(size_t)m0 * DM + d]);

    for (int i = 0; i < CLEN; i++) {
        int m = m0 + i;
        float de_n = 0.f, xc_n = 0.f;
        if (i + 1 < CLEN) {
            de_n = g_delta[(size_t)(m + 1) * DM + d];
            xc_n = __half2float(g_xch[(size_t)(m + 1) * DM + d]);
        }
        float dx = de * xc;
        sp += de;
        float pw[NST];
        da_powers(a, de, pw);
        const float4* bp = (const float4*)(g_ssm + (size_t)m * SSMW + DTRANK);
#pragma unroll
        for (int q = 0; q < 4; q++) {
            float4 bv = bp[q];
            h[4*q+0] = fmaf(pw[4*q+0], h[4*q+0], dx * bv.x);
            h[4*q+1] = fmaf(pw[4*q+1], h[4*q+1], dx * bv.y);
            h[4*q+2] = fmaf(pw[4*q+2], h[4*q+2], dx * bv.z);
            h[4*q+3] = fmaf(pw[4*q+3], h[4*q+3], dx * bv.w);
        }
        de = de_n; xc = xc_n;
    }
    g_sp[(size_t)(b * NCHNK + c) * DM + d] = sp;
    size_t base = (size_t)((b * NCHNK + c) * NST) * DM + d;
#pragma unroll
    for (int n = 0; n < NST; n++) g_hend[base + (size_t)n * DM] = h[n];
}

__global__ void scan_combine(const float* __restrict__ A_log)
{
    int gid = blockIdx.x * blockDim.x + threadIdx.x;
    if (gid >= NST * BSZ * DM) return;
    int d   = gid % DM;
    int rem = gid / DM;
    int b   = rem % BSZ;
    int n   = rem / BSZ;

    float Acn = -__expf(A_log[n]);

    float h = 0.f;
    size_t spb = (size_t)b * NCHNK * DM + d;
    size_t hb  = ((size_t)b * NCHNK * NST + n) * DM + d;

    float spv = g_sp[spb];
    float he  = g_hend[hb];
#pragma unroll 4
    for (int c = 0; c < NCHNK; c++) {
        float sp_n = 0.f, he_n = 0.f;
        if (c + 1 < NCHNK) {
            sp_n = g_sp[spb + (size_t)(c + 1) * DM];
            he_n = g_hend[hb + (size_t)(c + 1) * NST * DM];
        }
        g_hinit[hb + (size_t)c * NST * DM] = h;
        h = fmaf(__expf(Acn * spv), h, he);
        spv = sp_n; he = he_n;
    }
}

__global__ void scan_passB(const float* __restrict__ A_log, const float* __restrict__ D_param)
{
    int gid = blockIdx.x * blockDim.x + threadIdx.x;
    if (gid >= BSZ * NCHNK * DM) return;
    int d = gid % DM;
    int r = gid / DM;
    int c = r % NCHNK;
    int b = r / NCHNK;

    AConsts a = load_aconsts(A_log);
    float h[NST];
    size_t base = (size_t)((b * NCHNK + c) * NST) * DM + d;
#pragma unroll
    for (int n = 0; n < NST; n++) h[n] = g_hinit[base + (size_t)n * DM];

    float Dp = D_param[d];
    int m0 = b * TLEN + c * CLEN;

    float de = g_delta[(size_t)m0 * DM + d];
    float xc = __half2float(g_xch[(size_t)m0 * DM + d]);
    float gate = __half2float(g_gateh[(size_t)m0 * DM + d]);

    for (int i = 0; i < CLEN; i++) {
        int m = m0 + i;
        float de_n = 0.f, xc_n = 0.f, gate_n = 0.f;
        if (i + 1 < CLEN) {
            de_n = g_delta[(size_t)(m + 1) * DM + d];
            xc_n = __half2float(g_xch[(size_t)(m + 1) * DM + d]);
            gate_n = __half2float(g_gateh[(size_t)(m + 1) * DM + d]);
        }
        float dx = de * xc;
        float pw[NST];
        da_powers(a, de, pw);
        const float4* bp = (const float4*)(g_ssm + (size_t)m * SSMW + DTRANK);
        const float4* cp = (const float4*)(g_ssm + (size_t)m * SSMW + DTRANK + NST);
        float y = 0.f;
#pragma unroll
        for (int q = 0; q < 4; q++) {
            float4 bv = bp[q];
            float4 cv = cp[q];
            h[4*q+0] = fmaf(pw[4*q+0], h[4*q+0], dx * bv.x); y = fmaf(h[4*q+0], cv.x, y);
            h[4*q+1] = fmaf(pw[4*q+1], h[4*q+1], dx * bv.y); y = fmaf(h[4*q+1], cv.y, y);
            h[4*q+2] = fmaf(pw[4*q+2], h[4*q+2], dx * bv.z); y = fmaf(h[4*q+2], cv.z, y);
            h[4*q+3] = fmaf(pw[4*q+3], h[4*q+3], dx * bv.w); y = fmaf(h[4*q+3], cv.w, y);
        }
        y = fmaf(xc, Dp, y);
        g_A2h[(size_t)m * 2 * DM + d] = __float2half(y * gate);
        de = de_n; xc = xc_n; gate = gate_n;
    }
}

// ---------------- host launcher ---------------------------------------------
extern "C" void kernel_launch(void* const* d_in, const int* in_sizes, int n_in,
                              void* d_out, int out_size)
{
    const float* x        = (const float*)d_in[0];
    const float* in_w     = (const float*)d_in[1];
    const float* in_b     = (const float*)d_in[2];
    const float* conv_w   = (const float*)d_in[3];
    const float* conv_b   = (const float*)d_in[4];
    const float* xproj_w  = (const float*)d_in[5];
    const float* xproj_b  = (const float*)d_in[6];
    const float* dt_w     = (const float*)d_in[7];
    const float* dt_b     = (const float*)d_in[8];
    const float* A_log    = (const float*)d_in[9];
    const float* D_param  = (const float*)d_in[10];
    const float* out_w    = (const float*)d_in[11];
    const float* out_b    = (const float*)d_in[12];
    const float* skip_w   = (const float*)d_in[13];
    const float* skip_b   = (const float*)d_in[14];
    float* out = (float*)d_out;

    float *p_part, *p_delta;
    __half *p_xch, *p_dth, *p_A2h, *p_Binh, *p_Bxph, *p_Bdth, *p_B2h;
    cudaGetSymbolAddress((void**)&p_part,  g_part);
    cudaGetSymbolAddress((void**)&p_delta, g_delta);
    cudaGetSymbolAddress((void**)&p_xch,   g_xch);
    cudaGetSymbolAddress((void**)&p_dth,   g_dth);
    cudaGetSymbolAddress((void**)&p_A2h,   g_A2h);
    cudaGetSymbolAddress((void**)&p_Binh,  g_Binh);
    cudaGetSymbolAddress((void**)&p_Bxph,  g_Bxph);
    cudaGetSymbolAddress((void**)&p_Bdth,  g_Bdth);
    cudaGetSymbolAddress((void**)&p_B2h,   g_B2h);

    cudaFuncSetAttribute((const void*)gemm_mma<0,128>, cudaFuncAttributeMaxDynamicSharedMemorySize, GSMEM128);
    cudaFuncSetAttribute((const void*)gemm_mma<5,64>,  cudaFuncAttributeMaxDynamicSharedMemorySize, GSMEM64);
    cudaFuncSetAttribute((const void*)gemm_mma<2,64>,  cudaFuncAttributeMaxDynamicSharedMemorySize, GSMEM64);
    cudaFuncSetAttribute((const void*)gemm_mma<4,128>, cudaFuncAttributeMaxDynamicSharedMemorySize, GSMEM128);

    // 0) converts
    {
        const int total = (MTOT * DM + 2 * DM * DM + SSMW * DM + DM * DTRANK + DM * DM) / 4;
        prep_all<<<(total + 255) / 256, 256>>>(x, in_w, xproj_w, dt_w, out_w, skip_w);
    }
    // 1) in_proj -> g_xinh + g_gateh
    {
        dim3 g(2 * DM / 128, MTOT / 128);
        gemm_mma<4,128><<<g, 256, GSMEM128>>>(p_A2h + DM, 2 * DM, p_Binh, DM,
                                              2 * DM, DM / 64, in_b, nullptr,
                                              nullptr, 0, nullptr);
    }
    // 2) conv + silu
    conv_silu<<<(BSZ * (DM / 4) * TCH) / 256, 256>>>(conv_w, conv_b);
    // 3) x_proj split-K4 + reduce
    {
        dim3 g(1, MTOT / 64, XPK);
        gemm_mma<5,64><<<g, 256, GSMEM64>>>(p_xch, DM, p_Bxph, DM,
                                            SSMW, DM / (64 * XPK), nullptr, nullptr,
                                            p_part, SSMW, nullptr);
        xp_reduce<<<(MTOT * SSMW / 4 + 255) / 256, 256>>>(xproj_b);
    }
    // 4) dt_proj (BM=64: 512 CTAs, better chip fill)
    {
        dim3 g(DM / 128, MTOT / 64);
        gemm_mma<2,64><<<g, 256, GSMEM64>>>(p_dth, DTRANK, p_Bdth, DTRANK,
                                            DM, 1, dt_b, nullptr,
                                            p_delta, DM, nullptr);
    }
    // 5) scan
    scan_passA<<<(BSZ * NCHNK * DM) / 256, 256>>>(A_log);
    scan_combine<<<(NST * BSZ * DM) / 256, 256>>>(A_log);
    scan_passB<<<(BSZ * NCHNK * DM) / 256, 256>>>(A_log, D_param);
    // 6) fused out+skip
    {
        dim3 g(DM / 128, MTOT / 128);
        gemm_mma<0,128><<<g, 256, GSMEM128>>>(p_A2h, 2 * DM, p_B2h, 2 * DM,
                                              DM, 2 * DM / 64, out_b, skip_b,
                                              out, DM, nullptr);
    }
}

// round 14
// speedup vs baseline: 1.0352x; 1.0352x over previous
#include <cuda_runtime.h>
#include <cuda_fp16.h>
#include <math.h>
#include <stdint.h>

// ---------------- problem dims ----------------
#define BSZ    2
#define TLEN   2048
#define DM     1024
#define NST    16
#define DTRANK 64
#define SSMW   96
#define MTOT   (BSZ*TLEN)     // 4096
#define NCHNK  32
#define CLEN   (TLEN/NCHNK)   // 64
#define TCH    128
#define TLCH   (TLEN/TCH)     // 16
#define XPK    4              // x_proj split-K slices

// ---------------- device scratch (no allocations) ----------------
__device__ __half g_xinh[(size_t)MTOT * DM];
__device__ __half g_gateh[(size_t)MTOT * DM];
__device__ __half g_xch [(size_t)MTOT * DM];
__device__ float g_ssm  [(size_t)MTOT * SSMW];
__device__ float g_part [(size_t)XPK * MTOT * SSMW];
__device__ __half g_dth [(size_t)MTOT * DTRANK];
__device__ float g_delta[(size_t)MTOT * DM];
__device__ float g_sp   [(size_t)BSZ * NCHNK * DM];
__device__ float g_hend [(size_t)BSZ * NCHNK * DM * NST];   // [b][c][d][n]
__device__ float g_hinit[(size_t)BSZ * NCHNK * DM * NST];   // [b][c][d][n]
__device__ __half g_A2h [(size_t)MTOT * 2 * DM];   // [y | x]
__device__ __half g_Binh[(size_t)2 * DM * DM];
__device__ __half g_Bxph[(size_t)SSMW * DM];
__device__ __half g_Bdth[(size_t)DM * DTRANK];
__device__ __half g_B2h [(size_t)DM * 2 * DM];     // row n: [Wout_n | Wskip_n]

// ---------------- helpers ----------------
__device__ __forceinline__ uint32_t smem_u32(const void* p) {
    uint32_t a;
    asm("{ .reg .u64 t; cvta.to.shared.u64 t, %1; cvt.u32.u64 %0, t; }" : "=r"(a) : "l"(p));
    return a;
}
#define SW128(o) ((o) ^ (((o) >> 3) & 0x70))

__device__ __forceinline__ void ldm_x4(uint32_t* r, uint32_t addr) {
    asm volatile("ldmatrix.sync.aligned.m8n8.x4.shared.b16 {%0,%1,%2,%3}, [%4];"
                 : "=r"(r[0]), "=r"(r[1]), "=r"(r[2]), "=r"(r[3]) : "r"(addr));
}
__device__ __forceinline__ void mma_f16(float* d, const uint32_t* a, const uint32_t* b) {
    asm volatile("mma.sync.aligned.m16n8k16.row.col.f32.f16.f16.f32 "
                 "{%0,%1,%2,%3}, {%4,%5,%6,%7}, {%8,%9}, {%0,%1,%2,%3};"
                 : "+f"(d[0]), "+f"(d[1]), "+f"(d[2]), "+f"(d[3])
                 : "r"(a[0]), "r"(a[1]), "r"(a[2]), "r"(a[3]), "r"(b[0]), "r"(b[1]));
}
__device__ __forceinline__ uint32_t pack2h(float a, float b) {
    __half2 h = __floats2half2_rn(a, b);
    return *(uint32_t*)&h;
}
__device__ __forceinline__ float softplus_f(float v) {
    return (v > 20.f) ? v : __logf(1.f + __expf(v));
}
__device__ __forceinline__ float silu_f(float v) {
    return v / (1.f + __expf(-v));
}

// ---------------- HMMA fp16 GEMM ----------------
// MODE 0: C = acc + bias (+ bias2)      (out+skip fused)
// MODE 2: delta = softplus(acc+bias)    (dt_proj)
// MODE 4: in_proj: x_in -> g_xinh ; res -> silu -> g_gateh
// MODE 5: x_proj split-K partial
template<int MODE, int BM>
__global__ void __launch_bounds__(256, 2)
gemm_mma(const __half* __restrict__ A, int lda,
         const __half* __restrict__ B, int ldb,
         int Ntot, int KT,
         const float* __restrict__ bias, const float* __restrict__ bias2,
         float* __restrict__ C, int ldc,
         __half* __restrict__ dth)
{
    constexpr int ABYTES = BM * 128;
    constexpr int STG    = ABYTES + 16384;
    constexpr int NT     = (BM == 128) ? 8 : 4;
    constexpr int STAGES = (BM == 128) ? 3 : 4;

    extern __shared__ char smem[];
    const uint32_t sb  = smem_u32(smem);
    const int tid  = threadIdx.x;
    const int wid  = tid >> 5;
    const int lane = tid & 31;
    const int bm   = blockIdx.y * BM;
    const int bn   = blockIdx.x * 128;
    const int kbase = (MODE == 5) ? blockIdx.z * KT * 64 : 0;
    const int wrow = (BM == 128) ? (wid & 3) * 32 : (wid & 1) * 32;
    const int wcol = (BM == 128) ? (wid >> 2) * 64 : (wid >> 1) * 32;

    float acc[2][NT][4];
#pragma unroll
    for (int m = 0; m < 2; m++)
#pragma unroll
        for (int n = 0; n < NT; n++)
#pragma unroll
            for (int v = 0; v < 4; v++) acc[m][n][v] = 0.f;

    auto load_stage = [&](int kt, int s) {
        uint32_t stg = sb + s * STG;
        int koff = kbase + kt * 64;
#pragma unroll
        for (int i = 0; i < BM / 32; i++) {
            int chunk = tid + i * 256;
            int row = chunk >> 3, c16 = chunk & 7;
            uint32_t dst = stg + SW128(row * 128 + c16 * 16);
            const __half* src = A + (size_t)(bm + row) * lda + koff + c16 * 8;
            asm volatile("cp.async.cg.shared.global [%0], [%1], 16;"
                         :: "r"(dst), "l"(src) : "memory");
        }
#pragma unroll
        for (int i = 0; i < 4; i++) {
            int chunk = tid + i * 256;
            int row = chunk >> 3, c16 = chunk & 7;
            uint32_t dst = stg + ABYTES + SW128(row * 128 + c16 * 16);
            int gr = bn + row;
            int sz = 16;
            if (gr >= Ntot) { gr = 0; sz = 0; }
            const __half* src = B + (size_t)gr * ldb + koff + c16 * 8;
            asm volatile("cp.async.cg.shared.global [%0], [%1], 16, %2;"
                         :: "r"(dst), "l"(src), "r"(sz) : "memory");
        }
        asm volatile("cp.async.commit_group;" ::: "memory");
    };

    const int g = lane >> 3, r = lane & 7;
    const uint32_t aoff0 = (wrow + (g & 1) * 8 + r) * 128 + (g >> 1) * 16;
    const uint32_t boff0 = (wcol + (g >> 1) * 8 + r) * 128 + (g & 1) * 16;

    uint32_t afr[2][2][4];
    uint32_t bfr[2][NT][2];

    auto ld_frags = [&](uint32_t stg, int ks, int buf) {
        const int kByte = ks * 32;
#pragma unroll
        for (int m = 0; m < 2; m++)
            ldm_x4(afr[buf][m], stg + SW128(aoff0 + m * 16 * 128 + kByte));
#pragma unroll
        for (int nb = 0; nb < NT / 2; nb++) {
            uint32_t t[4];
            ldm_x4(t, stg + ABYTES + SW128(boff0 + nb * 16 * 128 + kByte));
            bfr[buf][nb * 2][0] = t[0]; bfr[buf][nb * 2][1] = t[1];
            bfr[buf][nb * 2 + 1][0] = t[2]; bfr[buf][nb * 2 + 1][1] = t[3];
        }
    };
    auto do_mma = [&](int buf) {
#pragma unroll
        for (int m = 0; m < 2; m++)
#pragma unroll
            for (int n = 0; n < NT; n++)
                mma_f16(acc[m][n], afr[buf][m], bfr[buf][n]);
    };

    int pf = KT < (STAGES - 1) ? KT : (STAGES - 1);
    for (int s = 0; s < pf; s++) load_stage(s, s);

    for (int kt = 0; kt < KT; kt++) {
        int w = KT - kt - 1;
        if (w > STAGES - 2) w = STAGES - 2;
        if (w == 0)      asm volatile("cp.async.wait_group 0;" ::: "memory");
        else if (w == 1) asm volatile("cp.async.wait_group 1;" ::: "memory");
        else             asm volatile("cp.async.wait_group 2;" ::: "memory");
        __syncthreads();
        if (kt + STAGES - 1 < KT) load_stage(kt + STAGES - 1, (kt + STAGES - 1) % STAGES);

        uint32_t stg = sb + (kt % STAGES) * STG;
        ld_frags(stg, 0, 0);
#pragma unroll
        for (int ks = 0; ks < 4; ks++) {
            int cur = ks & 1;
            if (ks < 3) ld_frags(stg, ks + 1, cur ^ 1);
            do_mma(cur);
        }
    }
    __syncthreads();

    float* epi = (float*)smem;
#pragma unroll
    for (int m = 0; m < 2; m++)
#pragma unroll
        for (int n = 0; n < NT; n++) {
            int row = wrow + m * 16 + (lane >> 2);
            int col = wcol + n * 8 + (lane & 3) * 2;
            epi[row * 128 + col]           = acc[m][n][0];
            epi[row * 128 + col + 1]       = acc[m][n][1];
            epi[(row + 8) * 128 + col]     = acc[m][n][2];
            epi[(row + 8) * 128 + col + 1] = acc[m][n][3];
        }
    __syncthreads();

    const float4* epi4 = (const float4*)epi;
    constexpr int EIT = BM / 8;
    if (MODE == 0) {
#pragma unroll 4
        for (int i = 0; i < EIT; i++) {
            int e = tid + i * 256;
            int row = e >> 5, c4 = e & 31;
            float4 v = epi4[e];
            int n = bn + c4 * 4;
            v.x += bias[n + 0]; v.y += bias[n + 1]; v.z += bias[n + 2]; v.w += bias[n + 3];
            if (bias2) {
                v.x += bias2[n + 0]; v.y += bias2[n + 1]; v.z += bias2[n + 2]; v.w += bias2[n + 3];
            }
            *(float4*)(C + (size_t)(bm + row) * ldc + n) = v;
        }
    } else if (MODE == 4) {
#pragma unroll 4
        for (int i = 0; i < EIT; i++) {
            int e = tid + i * 256;
            int row = e >> 5, c4 = e & 31;
            float4 v = epi4[e];
            int n = bn + c4 * 4;
            v.x += bias[n + 0]; v.y += bias[n + 1]; v.z += bias[n + 2]; v.w += bias[n + 3];
            if (bn < DM) {
                uint2 pk = make_uint2(pack2h(v.x, v.y), pack2h(v.z, v.w));
                *(uint2*)(g_xinh + (size_t)(bm + row) * DM + n) = pk;
            } else {
                uint2 pk = make_uint2(pack2h(silu_f(v.x), silu_f(v.y)),
                                      pack2h(silu_f(v.z), silu_f(v.w)));
                *(uint2*)(g_gateh + (size_t)(bm + row) * DM + (n - DM)) = pk;
            }
        }
    } else if (MODE == 2) {
#pragma unroll 4
        for (int i = 0; i < EIT; i++) {
            int e = tid + i * 256;
            int row = e >> 5, c4 = e & 31;
            float4 v = epi4[e];
            int n = bn + c4 * 4;
            v.x += bias[n + 0]; v.y += bias[n + 1]; v.z += bias[n + 2]; v.w += bias[n + 3];
            float4 sp;
            sp.x = softplus_f(v.x);
            sp.y = softplus_f(v.y);
            sp.z = softplus_f(v.z);
            sp.w = softplus_f(v.w);
            *(float4*)(C + (size_t)(bm + row) * DM + n) = sp;
        }
    } else { // MODE 5
        float* part = C + (size_t)blockIdx.z * MTOT * SSMW;
        for (int i = 0; i < EIT; i++) {
            int e = tid + i * 256;
            int row = e >> 5, c4 = e & 31;
            if (c4 >= 24) continue;
            float4 v = epi4[e];
            *(float4*)(part + (size_t)(bm + row) * SSMW + c4 * 4) = v;
        }
    }
}

#define GSMEM128 (3 * (128 * 128 + 16384))   // 98304
#define GSMEM64  (4 * (64 * 128 + 16384))    // 98304

// ---------------- x_proj split-K reduce (float4) ----------------
__global__ void xp_reduce(const float* __restrict__ xproj_b)
{
    int i4 = blockIdx.x * 256 + threadIdx.x;
    if (i4 >= MTOT * SSMW / 4) return;
    int i = i4 * 4;
    int m = i / SSMW, c = i % SSMW;
    float4 s = *(const float4*)(xproj_b + c);
#pragma unroll
    for (int z = 0; z < XPK; z++) {
        float4 p = *(const float4*)(g_part + (size_t)z * MTOT * SSMW + i);
        s.x += p.x; s.y += p.y; s.z += p.z; s.w += p.w;
    }
    *(float4*)(g_ssm + i) = s;
    if (c < DTRANK) {
        uint2 pk = make_uint2(pack2h(s.x, s.y), pack2h(s.z, s.w));
        *(uint2*)(g_dth + (size_t)m * DTRANK + c) = pk;
    }
}

// ---------------- fused converts (float4 vectorized) ----------------
__global__ void prep_all(const float* __restrict__ x, const float* __restrict__ in_w,
                         const float* __restrict__ xproj_w, const float* __restrict__ dt_w,
                         const float* __restrict__ out_w, const float* __restrict__ skip_w)
{
    const int NX  = MTOT * DM / 4;
    const int NIN = 2 * DM * DM / 4;
    const int NXP = SSMW * DM / 4;
    const int NDT = DM * DTRANK / 4;
    const int NO  = DM * DM / 4;
    int i = blockIdx.x * 256 + threadIdx.x;
    if (i < NX) {
        int e = i * 4;
        int m = e >> 10, c = e & 1023;
        float4 v = *(const float4*)(x + e);
        *(uint2*)(g_A2h + (size_t)m * 2048 + 1024 + c) =
            make_uint2(pack2h(v.x, v.y), pack2h(v.z, v.w));
        return;
    }
    i -= NX;
    if (i < NIN) {
        float4 v = *(const float4*)(in_w + i * 4);
        *(uint2*)(g_Binh + i * 4) = make_uint2(pack2h(v.x, v.y), pack2h(v.z, v.w));
        return;
    }
    i -= NIN;
    if (i < NXP) {
        float4 v = *(const float4*)(xproj_w + i * 4);
        *(uint2*)(g_Bxph + i * 4) = make_uint2(pack2h(v.x, v.y), pack2h(v.z, v.w));
        return;
    }
    i -= NXP;
    if (i < NDT) {
        float4 v = *(const float4*)(dt_w + i * 4);
        *(uint2*)(g_Bdth + i * 4) = make_uint2(pack2h(v.x, v.y), pack2h(v.z, v.w));
        return;
    }
    i -= NDT;
    if (i < NO) {
        int e = i * 4;
        int m = e >> 10, c = e & 1023;
        size_t o = (size_t)m * 2048;
        float4 v = *(const float4*)(out_w + e);
        *(uint2*)(g_B2h + o + c) = make_uint2(pack2h(v.x, v.y), pack2h(v.z, v.w));
        v = *(const float4*)(skip_w + e);
        *(uint2*)(g_B2h + o + 1024 + c) = make_uint2(pack2h(v.x, v.y), pack2h(v.z, v.w));
    }
}

// ---------------- depthwise causal conv (k=4) + silu, 4 channels/thread -----
__global__ void conv_silu(const float* __restrict__ cw, const float* __restrict__ cb)
{
    int gid = blockIdx.x * blockDim.x + threadIdx.x;
    if (gid >= BSZ * (DM / 4) * TCH) return;
    int d4 = gid % (DM / 4);
    int r  = gid / (DM / 4);
    int tc = r % TCH;
    int b  = r / TCH;
    int d  = d4 * 4;

    float w[4][4], bs[4];
#pragma unroll
    for (int j = 0; j < 4; j++) {
        float4 wv = *(const float4*)(cw + (d + j) * 4);
        w[j][0] = wv.x; w[j][1] = wv.y; w[j][2] = wv.z; w[j][3] = wv.w;
        bs[j] = cb[d + j];
    }
    int t0 = tc * TLCH;

    const uint2* xin = (const uint2*)g_xinh + (size_t)b * TLEN * (DM / 4) + d4;
    uint2* xout = (uint2*)g_xch + (size_t)b * TLEN * (DM / 4) + d4;

    auto unpk = [](uint2 u, float* f) {
        __half2 lo = *(__half2*)&u.x, hi = *(__half2*)&u.y;
        float2 a = __half22float2(lo), c = __half22float2(hi);
        f[0] = a.x; f[1] = a.y; f[2] = c.x; f[3] = c.y;
    };

    float hist[3][4];
#pragma unroll
    for (int k = 0; k < 3; k++)
#pragma unroll
        for (int j = 0; j < 4; j++) hist[k][j] = 0.f;
    if (t0 - 3 >= 0) unpk(xin[(size_t)(t0 - 3) * (DM / 4)], hist[0]);
    if (t0 - 2 >= 0) unpk(xin[(size_t)(t0 - 2) * (DM / 4)], hist[1]);
    if (t0 - 1 >= 0) unpk(xin[(size_t)(t0 - 1) * (DM / 4)], hist[2]);

#pragma unroll 4
    for (int i = 0; i < TLCH; i++) {
        int t = t0 + i;
        float x0[4];
        unpk(xin[(size_t)t * (DM / 4)], x0);
        float s[4];
#pragma unroll
        for (int j = 0; j < 4; j++) {
            float a = bs[j];
            a = fmaf(w[j][0], hist[0][j], a);
            a = fmaf(w[j][1], hist[1][j], a);
            a = fmaf(w[j][2], hist[2][j], a);
            a = fmaf(w[j][3], x0[j], a);
            s[j] = silu_f(a);
        }
        xout[(size_t)t * (DM / 4)] = make_uint2(pack2h(s[0], s[1]), pack2h(s[2], s[3]));
#pragma unroll
        for (int j = 0; j < 4; j++) {
            hist[0][j] = hist[1][j]; hist[1][j] = hist[2][j]; hist[2][j] = x0[j];
        }
    }
}

// ---------------- dA powers ----------------
struct AConsts {
    float Ac[NST];
    float Ac0;
    bool  geom;
};
__device__ __forceinline__ AConsts load_aconsts(const float* A_log) {
    AConsts a;
#pragma unroll
    for (int n = 0; n < NST; n++) a.Ac[n] = -__expf(A_log[n]);
    a.Ac0 = a.Ac[0];
    a.geom = true;
#pragma unroll
    for (int n = 0; n < NST; n++)
        a.geom = a.geom && (fabsf(a.Ac[n] - (float)(n + 1) * a.Ac0) <= 1e-5f * fabsf(a.Ac[n]));
    return a;
}
__device__ __forceinline__ void da_powers(const AConsts& a, float de, float* pw) {
    if (a.geom) {
        float r = __expf(a.Ac0 * de);
        pw[0] = r;
        pw[1] = pw[0] * pw[0];  pw[2] = pw[1] * pw[0];  pw[3] = pw[1] * pw[1];
        pw[4] = pw[2] * pw[1];  pw[5] = pw[2] * pw[2];  pw[6] = pw[3] * pw[2];
        pw[7] = pw[3] * pw[3];  pw[8] = pw[4] * pw[3];  pw[9] = pw[4] * pw[4];
        pw[10] = pw[5] * pw[4]; pw[11] = pw[5] * pw[5]; pw[12] = pw[6] * pw[5];
        pw[13] = pw[6] * pw[6]; pw[14] = pw[7] * pw[6]; pw[15] = pw[7] * pw[7];
    } else {
#pragma unroll
        for (int n = 0; n < NST; n++) pw[n] = __expf(a.Ac[n] * de);
    }
}

// ---------------- chunked selective scan (state layout [b][c][d][n]) --------
__global__ void scan_passA(const float* __restrict__ A_log)
{
    int gid = blockIdx.x * blockDim.x + threadIdx.x;
    if (gid >= BSZ * NCHNK * DM) return;
    int d = gid % DM;
    int r = gid / DM;
    int c = r % NCHNK;
    int b = r / NCHNK;

    AConsts a = load_aconsts(A_log);
    float h[NST];
#pragma unroll
    for (int n = 0; n < NST; n++) h[n] = 0.f;
    float sp = 0.f;

    int m0 = b * TLEN + c * CLEN;
    float de = g_delta[(size_t)m0 * DM + d];
    float xc = __half2float(g_xch[(size_t)m0 * DM + d]);

    for (int i = 0; i < CLEN; i++) {
        int m = m0 + i;
        float de_n = 0.f, xc_n = 0.f;
        if (i + 1 < CLEN) {
            de_n = g_delta[(size_t)(m + 1) * DM + d];
            xc_n = __half2float(g_xch[(size_t)(m + 1) * DM + d]);
        }
        float dx = de * xc;
        sp += de;
        float pw[NST];
        da_powers(a, de, pw);
        const float4* bp = (const float4*)(g_ssm + (size_t)m * SSMW + DTRANK);
#pragma unroll
        for (int q = 0; q < 4; q++) {
            float4 bv = bp[q];
            h[4*q+0] = fmaf(pw[4*q+0], h[4*q+0], dx * bv.x);
            h[4*q+1] = fmaf(pw[4*q+1], h[4*q+1], dx * bv.y);
            h[4*q+2] = fmaf(pw[4*q+2], h[4*q+2], dx * bv.z);
            h[4*q+3] = fmaf(pw[4*q+3], h[4*q+3], dx * bv.w);
        }
        de = de_n; xc = xc_n;
    }
    g_sp[(size_t)(b * NCHNK + c) * DM + d] = sp;
    float4* he = (float4*)(g_hend + ((size_t)(b * NCHNK + c) * DM + d) * NST);
#pragma unroll
    for (int q = 0; q < 4; q++)
        he[q] = make_float4(h[4*q+0], h[4*q+1], h[4*q+2], h[4*q+3]);
}

// combine: thread per (b,d,n), n fastest for coalescing
__global__ void scan_combine(const float* __restrict__ A_log)
{
    int gid = blockIdx.x * blockDim.x + threadIdx.x;
    if (gid >= BSZ * DM * NST) return;
    int n   = gid % NST;
    int rem = gid / NST;
    int d   = rem % DM;
    int b   = rem / DM;

    float Acn = -__expf(A_log[n]);

    float h = 0.f;
    size_t spb = (size_t)b * NCHNK * DM + d;
    size_t hb  = ((size_t)(b * NCHNK) * DM + d) * NST + n;   // stride per c: DM*NST

    float spv = g_sp[spb];
    float he  = g_hend[hb];
#pragma unroll 4
    for (int c = 0; c < NCHNK; c++) {
        float sp_n = 0.f, he_n = 0.f;
        if (c + 1 < NCHNK) {
            sp_n = g_sp[spb + (size_t)(c + 1) * DM];
            he_n = g_hend[hb + (size_t)(c + 1) * DM * NST];
        }
        g_hinit[hb + (size_t)c * DM * NST] = h;
        h = fmaf(__expf(Acn * spv), h, he);
        spv = sp_n; he = he_n;
    }
}

__global__ void scan_passB(const float* __restrict__ A_log, const float* __restrict__ D_param)
{
    int gid = blockIdx.x * blockDim.x + threadIdx.x;
    if (gid >= BSZ * NCHNK * DM) return;
    int d = gid % DM;
    int r = gid / DM;
    int c = r % NCHNK;
    int b = r / NCHNK;

    AConsts a = load_aconsts(A_log);
    float h[NST];
    const float4* hi4 = (const float4*)(g_hinit + ((size_t)(b * NCHNK + c) * DM + d) * NST);
#pragma unroll
    for (int q = 0; q < 4; q++) {
        float4 v = hi4[q];
        h[4*q+0] = v.x; h[4*q+1] = v.y; h[4*q+2] = v.z; h[4*q+3] = v.w;
    }

    float Dp = D_param[d];
    int m0 = b * TLEN + c * CLEN;

    float de = g_delta[(size_t)m0 * DM + d];
    float xc = __half2float(g_xch[(size_t)m0 * DM + d]);
    float gate = __half2float(g_gateh[(size_t)m0 * DM + d]);

    for (int i = 0; i < CLEN; i++) {
        int m = m0 + i;
        float de_n = 0.f, xc_n = 0.f, gate_n = 0.f;
        if (i + 1 < CLEN) {
            de_n = g_delta[(size_t)(m + 1) * DM + d];
            xc_n = __half2float(g_xch[(size_t)(m + 1) * DM + d]);
            gate_n = __half2float(g_gateh[(size_t)(m + 1) * DM + d]);
        }
        float dx = de * xc;
        float pw[NST];
        da_powers(a, de, pw);
        const float4* bp = (const float4*)(g_ssm + (size_t)m * SSMW + DTRANK);
        const float4* cp = (const float4*)(g_ssm + (size_t)m * SSMW + DTRANK + NST);
        float y = 0.f;
#pragma unroll
        for (int q = 0; q < 4; q++) {
            float4 bv = bp[q];
            float4 cv = cp[q];
            h[4*q+0] = fmaf(pw[4*q+0], h[4*q+0], dx * bv.x); y = fmaf(h[4*q+0], cv.x, y);
            h[4*q+1] = fmaf(pw[4*q+1], h[4*q+1], dx * bv.y); y = fmaf(h[4*q+1], cv.y, y);
            h[4*q+2] = fmaf(pw[4*q+2], h[4*q+2], dx * bv.z); y = fmaf(h[4*q+2], cv.z, y);
            h[4*q+3] = fmaf(pw[4*q+3], h[4*q+3], dx * bv.w); y = fmaf(h[4*q+3], cv.w, y);
        }
        y = fmaf(xc, Dp, y);
        g_A2h[(size_t)m * 2 * DM + d] = __float2half(y * gate);
        de = de_n; xc = xc_n; gate = gate_n;
    }
}

// ---------------- host launcher ---------------------------------------------
extern "C" void kernel_launch(void* const* d_in, const int* in_sizes, int n_in,
                              void* d_out, int out_size)
{
    const float* x        = (const float*)d_in[0];
    const float* in_w     = (const float*)d_in[1];
    const float* in_b     = (const float*)d_in[2];
    const float* conv_w   = (const float*)d_in[3];
    const float* conv_b   = (const float*)d_in[4];
    const float* xproj_w  = (const float*)d_in[5];
    const float* xproj_b  = (const float*)d_in[6];
    const float* dt_w     = (const float*)d_in[7];
    const float* dt_b     = (const float*)d_in[8];
    const float* A_log    = (const float*)d_in[9];
    const float* D_param  = (const float*)d_in[10];
    const float* out_w    = (const float*)d_in[11];
    const float* out_b    = (const float*)d_in[12];
    const float* skip_w   = (const float*)d_in[13];
    const float* skip_b   = (const float*)d_in[14];
    float* out = (float*)d_out;

    float *p_part, *p_delta;
    __half *p_xch, *p_dth, *p_A2h, *p_Binh, *p_Bxph, *p_Bdth, *p_B2h;
    cudaGetSymbolAddress((void**)&p_part,  g_part);
    cudaGetSymbolAddress((void**)&p_delta, g_delta);
    cudaGetSymbolAddress((void**)&p_xch,   g_xch);
    cudaGetSymbolAddress((void**)&p_dth,   g_dth);
    cudaGetSymbolAddress((void**)&p_A2h,   g_A2h);
    cudaGetSymbolAddress((void**)&p_Binh,  g_Binh);
    cudaGetSymbolAddress((void**)&p_Bxph,  g_Bxph);
    cudaGetSymbolAddress((void**)&p_Bdth,  g_Bdth);
    cudaGetSymbolAddress((void**)&p_B2h,   g_B2h);

    cudaFuncSetAttribute((const void*)gemm_mma<0,128>, cudaFuncAttributeMaxDynamicSharedMemorySize, GSMEM128);
    cudaFuncSetAttribute((const void*)gemm_mma<5,64>,  cudaFuncAttributeMaxDynamicSharedMemorySize, GSMEM64);
    cudaFuncSetAttribute((const void*)gemm_mma<2,128>, cudaFuncAttributeMaxDynamicSharedMemorySize, GSMEM128);
    cudaFuncSetAttribute((const void*)gemm_mma<4,128>, cudaFuncAttributeMaxDynamicSharedMemorySize, GSMEM128);

    // 0) converts
    {
        const int total = (MTOT * DM + 2 * DM * DM + SSMW * DM + DM * DTRANK + DM * DM) / 4;
        prep_all<<<(total + 255) / 256, 256>>>(x, in_w, xproj_w, dt_w, out_w, skip_w);
    }
    // 1) in_proj -> g_xinh + g_gateh
    {
        dim3 g(2 * DM / 128, MTOT / 128);
        gemm_mma<4,128><<<g, 256, GSMEM128>>>(p_A2h + DM, 2 * DM, p_Binh, DM,
                                              2 * DM, DM / 64, in_b, nullptr,
                                              nullptr, 0, nullptr);
    }
    // 2) conv + silu
    conv_silu<<<(BSZ * (DM / 4) * TCH) / 256, 256>>>(conv_w, conv_b);
    // 3) x_proj split-K4 + reduce
    {
        dim3 g(1, MTOT / 64, XPK);
        gemm_mma<5,64><<<g, 256, GSMEM64>>>(p_xch, DM, p_Bxph, DM,
                                            SSMW, DM / (64 * XPK), nullptr, nullptr,
                                            p_part, SSMW, nullptr);
        xp_reduce<<<(MTOT * SSMW / 4 + 255) / 256, 256>>>(xproj_b);
    }
    // 4) dt_proj
    {
        dim3 g(DM / 128, MTOT / 128);
        gemm_mma<2,128><<<g, 256, GSMEM128>>>(p_dth, DTRANK, p_Bdth, DTRANK,
                                              DM, 1, dt_b, nullptr,
                                              p_delta, DM, nullptr);
    }
    // 5) scan
    scan_passA<<<(BSZ * NCHNK * DM) / 256, 256>>>(A_log);
    scan_combine<<<(BSZ * DM * NST) / 256, 256>>>(A_log);
    scan_passB<<<(BSZ * NCHNK * DM) / 256, 256>>>(A_log, D_param);
    // 6) fused out+skip
    {
        dim3 g(DM / 128, MTOT / 128);
        gemm_mma<0,128><<<g, 256, GSMEM128>>>(p_A2h, 2 * DM, p_B2h, 2 * DM,
                                              DM, 2 * DM / 64, out_b, skip_b,
                                              out, DM, nullptr);
    }
}

// round 15
// speedup vs baseline: 1.0364x; 1.0012x over previous
#include <cuda_runtime.h>
#include <cuda_fp16.h>
#include <math.h>
#include <stdint.h>

// ---------------- problem dims ----------------
#define BSZ    2
#define TLEN   2048
#define DM     1024
#define NST    16
#define DTRANK 64
#define SSMW   96
#define MTOT   (BSZ*TLEN)     // 4096
#define NCHNK  32
#define CLEN   (TLEN/NCHNK)   // 64
#define TCH    128
#define TLCH   (TLEN/TCH)     // 16
#define XPK    4              // x_proj split-K slices

// ---------------- device scratch (no allocations) ----------------
__device__ __half g_xinh[(size_t)MTOT * DM];
__device__ __half g_gateh[(size_t)MTOT * DM];
__device__ __half g_xch [(size_t)MTOT * DM];
__device__ float g_ssm  [(size_t)MTOT * SSMW];
__device__ float g_part [(size_t)XPK * MTOT * SSMW];
__device__ __half g_dth [(size_t)MTOT * DTRANK];
__device__ __half g_deltah[(size_t)MTOT * DM];              // softplus(dt) fp16
__device__ float g_sp   [(size_t)BSZ * NCHNK * DM];
__device__ float g_hend [(size_t)BSZ * NCHNK * DM * NST];   // [b][c][d][n]
__device__ float g_hinit[(size_t)BSZ * NCHNK * DM * NST];   // [b][c][d][n]
__device__ __half g_A2h [(size_t)MTOT * 2 * DM];   // [y | x]
__device__ __half g_Binh[(size_t)2 * DM * DM];
__device__ __half g_Bxph[(size_t)SSMW * DM];
__device__ __half g_Bdth[(size_t)DM * DTRANK];
__device__ __half g_B2h [(size_t)DM * 2 * DM];     // row n: [Wout_n | Wskip_n]

// ---------------- helpers ----------------
__device__ __forceinline__ uint32_t smem_u32(const void* p) {
    uint32_t a;
    asm("{ .reg .u64 t; cvta.to.shared.u64 t, %1; cvt.u32.u64 %0, t; }" : "=r"(a) : "l"(p));
    return a;
}
#define SW128(o) ((o) ^ (((o) >> 3) & 0x70))

__device__ __forceinline__ void ldm_x4(uint32_t* r, uint32_t addr) {
    asm volatile("ldmatrix.sync.aligned.m8n8.x4.shared.b16 {%0,%1,%2,%3}, [%4];"
                 : "=r"(r[0]), "=r"(r[1]), "=r"(r[2]), "=r"(r[3]) : "r"(addr));
}
__device__ __forceinline__ void mma_f16(float* d, const uint32_t* a, const uint32_t* b) {
    asm volatile("mma.sync.aligned.m16n8k16.row.col.f32.f16.f16.f32 "
                 "{%0,%1,%2,%3}, {%4,%5,%6,%7}, {%8,%9}, {%0,%1,%2,%3};"
                 : "+f"(d[0]), "+f"(d[1]), "+f"(d[2]), "+f"(d[3])
                 : "r"(a[0]), "r"(a[1]), "r"(a[2]), "r"(a[3]), "r"(b[0]), "r"(b[1]));
}
__device__ __forceinline__ uint32_t pack2h(float a, float b) {
    __half2 h = __floats2half2_rn(a, b);
    return *(uint32_t*)&h;
}
__device__ __forceinline__ float softplus_f(float v) {
    return (v > 20.f) ? v : __logf(1.f + __expf(v));
}
__device__ __forceinline__ float silu_f(float v) {
    return v / (1.f + __expf(-v));
}

// ---------------- HMMA fp16 GEMM ----------------
// MODE 0: C = acc + bias (+ bias2)      (out+skip fused)
// MODE 2: delta = softplus(acc+bias) -> g_deltah fp16   (dt_proj)
// MODE 4: in_proj: x_in -> g_xinh ; res -> silu -> g_gateh
// MODE 5: x_proj split-K partial
template<int MODE, int BM>
__global__ void __launch_bounds__(256, 2)
gemm_mma(const __half* __restrict__ A, int lda,
         const __half* __restrict__ B, int ldb,
         int Ntot, int KT,
         const float* __restrict__ bias, const float* __restrict__ bias2,
         float* __restrict__ C, int ldc,
         __half* __restrict__ dth)
{
    constexpr int ABYTES = BM * 128;
    constexpr int STG    = ABYTES + 16384;
    constexpr int NT     = (BM == 128) ? 8 : 4;
    constexpr int STAGES = (BM == 128) ? 3 : 4;

    extern __shared__ char smem[];
    const uint32_t sb  = smem_u32(smem);
    const int tid  = threadIdx.x;
    const int wid  = tid >> 5;
    const int lane = tid & 31;
    const int bm   = blockIdx.y * BM;
    const int bn   = blockIdx.x * 128;
    const int kbase = (MODE == 5) ? blockIdx.z * KT * 64 : 0;
    const int wrow = (BM == 128) ? (wid & 3) * 32 : (wid & 1) * 32;
    const int wcol = (BM == 128) ? (wid >> 2) * 64 : (wid >> 1) * 32;

    float acc[2][NT][4];
#pragma unroll
    for (int m = 0; m < 2; m++)
#pragma unroll
        for (int n = 0; n < NT; n++)
#pragma unroll
            for (int v = 0; v < 4; v++) acc[m][n][v] = 0.f;

    auto load_stage = [&](int kt, int s) {
        uint32_t stg = sb + s * STG;
        int koff = kbase + kt * 64;
#pragma unroll
        for (int i = 0; i < BM / 32; i++) {
            int chunk = tid + i * 256;
            int row = chunk >> 3, c16 = chunk & 7;
            uint32_t dst = stg + SW128(row * 128 + c16 * 16);
            const __half* src = A + (size_t)(bm + row) * lda + koff + c16 * 8;
            asm volatile("cp.async.cg.shared.global [%0], [%1], 16;"
                         :: "r"(dst), "l"(src) : "memory");
        }
#pragma unroll
        for (int i = 0; i < 4; i++) {
            int chunk = tid + i * 256;
            int row = chunk >> 3, c16 = chunk & 7;
            uint32_t dst = stg + ABYTES + SW128(row * 128 + c16 * 16);
            int gr = bn + row;
            int sz = 16;
            if (gr >= Ntot) { gr = 0; sz = 0; }
            const __half* src = B + (size_t)gr * ldb + koff + c16 * 8;
            asm volatile("cp.async.cg.shared.global [%0], [%1], 16, %2;"
                         :: "r"(dst), "l"(src), "r"(sz) : "memory");
        }
        asm volatile("cp.async.commit_group;" ::: "memory");
    };

    const int g = lane >> 3, r = lane & 7;
    const uint32_t aoff0 = (wrow + (g & 1) * 8 + r) * 128 + (g >> 1) * 16;
    const uint32_t boff0 = (wcol + (g >> 1) * 8 + r) * 128 + (g & 1) * 16;

    uint32_t afr[2][2][4];
    uint32_t bfr[2][NT][2];

    auto ld_frags = [&](uint32_t stg, int ks, int buf) {
        const int kByte = ks * 32;
#pragma unroll
        for (int m = 0; m < 2; m++)
            ldm_x4(afr[buf][m], stg + SW128(aoff0 + m * 16 * 128 + kByte));
#pragma unroll
        for (int nb = 0; nb < NT / 2; nb++) {
            uint32_t t[4];
            ldm_x4(t, stg + ABYTES + SW128(boff0 + nb * 16 * 128 + kByte));
            bfr[buf][nb * 2][0] = t[0]; bfr[buf][nb * 2][1] = t[1];
            bfr[buf][nb * 2 + 1][0] = t[2]; bfr[buf][nb * 2 + 1][1] = t[3];
        }
    };
    auto do_mma = [&](int buf) {
#pragma unroll
        for (int m = 0; m < 2; m++)
#pragma unroll
            for (int n = 0; n < NT; n++)
                mma_f16(acc[m][n], afr[buf][m], bfr[buf][n]);
    };

    int pf = KT < (STAGES - 1) ? KT : (STAGES - 1);
    for (int s = 0; s < pf; s++) load_stage(s, s);

    for (int kt = 0; kt < KT; kt++) {
        int w = KT - kt - 1;
        if (w > STAGES - 2) w = STAGES - 2;
        if (w == 0)      asm volatile("cp.async.wait_group 0;" ::: "memory");
        else if (w == 1) asm volatile("cp.async.wait_group 1;" ::: "memory");
        else             asm volatile("cp.async.wait_group 2;" ::: "memory");
        __syncthreads();
        if (kt + STAGES - 1 < KT) load_stage(kt + STAGES - 1, (kt + STAGES - 1) % STAGES);

        uint32_t stg = sb + (kt % STAGES) * STG;
        ld_frags(stg, 0, 0);
#pragma unroll
        for (int ks = 0; ks < 4; ks++) {
            int cur = ks & 1;
            if (ks < 3) ld_frags(stg, ks + 1, cur ^ 1);
            do_mma(cur);
        }
    }
    __syncthreads();

    float* epi = (float*)smem;
#pragma unroll
    for (int m = 0; m < 2; m++)
#pragma unroll
        for (int n = 0; n < NT; n++) {
            int row = wrow + m * 16 + (lane >> 2);
            int col = wcol + n * 8 + (lane & 3) * 2;
            epi[row * 128 + col]           = acc[m][n][0];
            epi[row * 128 + col + 1]       = acc[m][n][1];
            epi[(row + 8) * 128 + col]     = acc[m][n][2];
            epi[(row + 8) * 128 + col + 1] = acc[m][n][3];
        }
    __syncthreads();

    const float4* epi4 = (const float4*)epi;
    constexpr int EIT = BM / 8;
    if (MODE == 0) {
#pragma unroll 4
        for (int i = 0; i < EIT; i++) {
            int e = tid + i * 256;
            int row = e >> 5, c4 = e & 31;
            float4 v = epi4[e];
            int n = bn + c4 * 4;
            v.x += bias[n + 0]; v.y += bias[n + 1]; v.z += bias[n + 2]; v.w += bias[n + 3];
            if (bias2) {
                v.x += bias2[n + 0]; v.y += bias2[n + 1]; v.z += bias2[n + 2]; v.w += bias2[n + 3];
            }
            *(float4*)(C + (size_t)(bm + row) * ldc + n) = v;
        }
    } else if (MODE == 4) {
#pragma unroll 4
        for (int i = 0; i < EIT; i++) {
            int e = tid + i * 256;
            int row = e >> 5, c4 = e & 31;
            float4 v = epi4[e];
            int n = bn + c4 * 4;
            v.x += bias[n + 0]; v.y += bias[n + 1]; v.z += bias[n + 2]; v.w += bias[n + 3];
            if (bn < DM) {
                uint2 pk = make_uint2(pack2h(v.x, v.y), pack2h(v.z, v.w));
                *(uint2*)(g_xinh + (size_t)(bm + row) * DM + n) = pk;
            } else {
                uint2 pk = make_uint2(pack2h(silu_f(v.x), silu_f(v.y)),
                                      pack2h(silu_f(v.z), silu_f(v.w)));
                *(uint2*)(g_gateh + (size_t)(bm + row) * DM + (n - DM)) = pk;
            }
        }
    } else if (MODE == 2) {
#pragma unroll 4
        for (int i = 0; i < EIT; i++) {
            int e = tid + i * 256;
            int row = e >> 5, c4 = e & 31;
            float4 v = epi4[e];
            int n = bn + c4 * 4;
            v.x += bias[n + 0]; v.y += bias[n + 1]; v.z += bias[n + 2]; v.w += bias[n + 3];
            uint2 pk = make_uint2(pack2h(softplus_f(v.x), softplus_f(v.y)),
                                  pack2h(softplus_f(v.z), softplus_f(v.w)));
            *(uint2*)(g_deltah + (size_t)(bm + row) * DM + n) = pk;
        }
    } else { // MODE 5
        float* part = C + (size_t)blockIdx.z * MTOT * SSMW;
        for (int i = 0; i < EIT; i++) {
            int e = tid + i * 256;
            int row = e >> 5, c4 = e & 31;
            if (c4 >= 24) continue;
            float4 v = epi4[e];
            *(float4*)(part + (size_t)(bm + row) * SSMW + c4 * 4) = v;
        }
    }
}

#define GSMEM128 (3 * (128 * 128 + 16384))   // 98304
#define GSMEM64  (4 * (64 * 128 + 16384))    // 98304

// ---------------- x_proj split-K reduce (float4) ----------------
__global__ void xp_reduce(const float* __restrict__ xproj_b)
{
    int i4 = blockIdx.x * 256 + threadIdx.x;
    if (i4 >= MTOT * SSMW / 4) return;
    int i = i4 * 4;
    int m = i / SSMW, c = i % SSMW;
    float4 s = *(const float4*)(xproj_b + c);
#pragma unroll
    for (int z = 0; z < XPK; z++) {
        float4 p = *(const float4*)(g_part + (size_t)z * MTOT * SSMW + i);
        s.x += p.x; s.y += p.y; s.z += p.z; s.w += p.w;
    }
    *(float4*)(g_ssm + i) = s;
    if (c < DTRANK) {
        uint2 pk = make_uint2(pack2h(s.x, s.y), pack2h(s.z, s.w));
        *(uint2*)(g_dth + (size_t)m * DTRANK + c) = pk;
    }
}

// ---------------- fused converts (float4 vectorized) ----------------
__global__ void prep_all(const float* __restrict__ x, const float* __restrict__ in_w,
                         const float* __restrict__ xproj_w, const float* __restrict__ dt_w,
                         const float* __restrict__ out_w, const float* __restrict__ skip_w)
{
    const int NX  = MTOT * DM / 4;
    const int NIN = 2 * DM * DM / 4;
    const int NXP = SSMW * DM / 4;
    const int NDT = DM * DTRANK / 4;
    const int NO  = DM * DM / 4;
    int i = blockIdx.x * 256 + threadIdx.x;
    if (i < NX) {
        int e = i * 4;
        int m = e >> 10, c = e & 1023;
        float4 v = *(const float4*)(x + e);
        *(uint2*)(g_A2h + (size_t)m * 2048 + 1024 + c) =
            make_uint2(pack2h(v.x, v.y), pack2h(v.z, v.w));
        return;
    }
    i -= NX;
    if (i < NIN) {
        float4 v = *(const float4*)(in_w + i * 4);
        *(uint2*)(g_Binh + i * 4) = make_uint2(pack2h(v.x, v.y), pack2h(v.z, v.w));
        return;
    }
    i -= NIN;
    if (i < NXP) {
        float4 v = *(const float4*)(xproj_w + i * 4);
        *(uint2*)(g_Bxph + i * 4) = make_uint2(pack2h(v.x, v.y), pack2h(v.z, v.w));
        return;
    }
    i -= NXP;
    if (i < NDT) {
        float4 v = *(const float4*)(dt_w + i * 4);
        *(uint2*)(g_Bdth + i * 4) = make_uint2(pack2h(v.x, v.y), pack2h(v.z, v.w));
        return;
    }
    i -= NDT;
    if (i < NO) {
        int e = i * 4;
        int m = e >> 10, c = e & 1023;
        size_t o = (size_t)m * 2048;
        float4 v = *(const float4*)(out_w + e);
        *(uint2*)(g_B2h + o + c) = make_uint2(pack2h(v.x, v.y), pack2h(v.z, v.w));
        v = *(const float4*)(skip_w + e);
        *(uint2*)(g_B2h + o + 1024 + c) = make_uint2(pack2h(v.x, v.y), pack2h(v.z, v.w));
    }
}

// ---------------- depthwise causal conv (k=4) + silu, 4 channels/thread -----
__global__ void conv_silu(const float* __restrict__ cw, const float* __restrict__ cb)
{
    int gid = blockIdx.x * blockDim.x + threadIdx.x;
    if (gid >= BSZ * (DM / 4) * TCH) return;
    int d4 = gid % (DM / 4);
    int r  = gid / (DM / 4);
    int tc = r % TCH;
    int b  = r / TCH;
    int d  = d4 * 4;

    float w[4][4], bs[4];
#pragma unroll
    for (int j = 0; j < 4; j++) {
        float4 wv = *(const float4*)(cw + (d + j) * 4);
        w[j][0] = wv.x; w[j][1] = wv.y; w[j][2] = wv.z; w[j][3] = wv.w;
        bs[j] = cb[d + j];
    }
    int t0 = tc * TLCH;

    const uint2* xin = (const uint2*)g_xinh + (size_t)b * TLEN * (DM / 4) + d4;
    uint2* xout = (uint2*)g_xch + (size_t)b * TLEN * (DM / 4) + d4;

    auto unpk = [](uint2 u, float* f) {
        __half2 lo = *(__half2*)&u.x, hi = *(__half2*)&u.y;
        float2 a = __half22float2(lo), c = __half22float2(hi);
        f[0] = a.x; f[1] = a.y; f[2] = c.x; f[3] = c.y;
    };

    float hist[3][4];
#pragma unroll
    for (int k = 0; k < 3; k++)
#pragma unroll
        for (int j = 0; j < 4; j++) hist[k][j] = 0.f;
    if (t0 - 3 >= 0) unpk(xin[(size_t)(t0 - 3) * (DM / 4)], hist[0]);
    if (t0 - 2 >= 0) unpk(xin[(size_t)(t0 - 2) * (DM / 4)], hist[1]);
    if (t0 - 1 >= 0) unpk(xin[(size_t)(t0 - 1) * (DM / 4)], hist[2]);

#pragma unroll 4
    for (int i = 0; i < TLCH; i++) {
        int t = t0 + i;
        float x0[4];
        unpk(xin[(size_t)t * (DM / 4)], x0);
        float s[4];
#pragma unroll
        for (int j = 0; j < 4; j++) {
            float a = bs[j];
            a = fmaf(w[j][0], hist[0][j], a);
            a = fmaf(w[j][1], hist[1][j], a);
            a = fmaf(w[j][2], hist[2][j], a);
            a = fmaf(w[j][3], x0[j], a);
            s[j] = silu_f(a);
        }
        xout[(size_t)t * (DM / 4)] = make_uint2(pack2h(s[0], s[1]), pack2h(s[2], s[3]));
#pragma unroll
        for (int j = 0; j < 4; j++) {
            hist[0][j] = hist[1][j]; hist[1][j] = hist[2][j]; hist[2][j] = x0[j];
        }
    }
}

// ---------------- dA powers ----------------
struct AConsts {
    float Ac[NST];
    float Ac0;
    bool  geom;
};
__device__ __forceinline__ AConsts load_aconsts(const float* A_log) {
    AConsts a;
#pragma unroll
    for (int n = 0; n < NST; n++) a.Ac[n] = -__expf(A_log[n]);
    a.Ac0 = a.Ac[0];
    a.geom = true;
#pragma unroll
    for (int n = 0; n < NST; n++)
        a.geom = a.geom && (fabsf(a.Ac[n] - (float)(n + 1) * a.Ac0) <= 1e-5f * fabsf(a.Ac[n]));
    return a;
}
__device__ __forceinline__ void da_powers(const AConsts& a, float de, float* pw) {
    if (a.geom) {
        float r = __expf(a.Ac0 * de);
        pw[0] = r;
        pw[1] = pw[0] * pw[0];  pw[2] = pw[1] * pw[0];  pw[3] = pw[1] * pw[1];
        pw[4] = pw[2] * pw[1];  pw[5] = pw[2] * pw[2];  pw[6] = pw[3] * pw[2];
        pw[7] = pw[3] * pw[3];  pw[8] = pw[4] * pw[3];  pw[9] = pw[4] * pw[4];
        pw[10] = pw[5] * pw[4]; pw[11] = pw[5] * pw[5]; pw[12] = pw[6] * pw[5];
        pw[13] = pw[6] * pw[6]; pw[14] = pw[7] * pw[6]; pw[15] = pw[7] * pw[7];
    } else {
#pragma unroll
        for (int n = 0; n < NST; n++) pw[n] = __expf(a.Ac[n] * de);
    }
}

// ---------------- chunked selective scan (state layout [b][c][d][n]) --------
__global__ void scan_passA(const float* __restrict__ A_log)
{
    int gid = blockIdx.x * blockDim.x + threadIdx.x;
    if (gid >= BSZ * NCHNK * DM) return;
    int d = gid % DM;
    int r = gid / DM;
    int c = r % NCHNK;
    int b = r / NCHNK;

    AConsts a = load_aconsts(A_log);
    float h[NST];
#pragma unroll
    for (int n = 0; n < NST; n++) h[n] = 0.f;
    float sp = 0.f;

    int m0 = b * TLEN + c * CLEN;
    float de = __half2float(g_deltah[(size_t)m0 * DM + d]);
    float xc = __half2float(g_xch[(size_t)m0 * DM + d]);

    for (int i = 0; i < CLEN; i++) {
        int m = m0 + i;
        float de_n = 0.f, xc_n = 0.f;
        if (i + 1 < CLEN) {
            de_n = __half2float(g_deltah[(size_t)(m + 1) * DM + d]);
            xc_n = __half2float(g_xch[(size_t)(m + 1) * DM + d]);
        }
        float dx = de * xc;
        sp += de;
        float pw[NST];
        da_powers(a, de, pw);
        const float4* bp = (const float4*)(g_ssm + (size_t)m * SSMW + DTRANK);
#pragma unroll
        for (int q = 0; q < 4; q++) {
            float4 bv = bp[q];
            h[4*q+0] = fmaf(pw[4*q+0], h[4*q+0], dx * bv.x);
            h[4*q+1] = fmaf(pw[4*q+1], h[4*q+1], dx * bv.y);
            h[4*q+2] = fmaf(pw[4*q+2], h[4*q+2], dx * bv.z);
            h[4*q+3] = fmaf(pw[4*q+3], h[4*q+3], dx * bv.w);
        }
        de = de_n; xc = xc_n;
    }
    g_sp[(size_t)(b * NCHNK + c) * DM + d] = sp;
    float4* he = (float4*)(g_hend + ((size_t)(b * NCHNK + c) * DM + d) * NST);
#pragma unroll
    for (int q = 0; q < 4; q++)
        he[q] = make_float4(h[4*q+0], h[4*q+1], h[4*q+2], h[4*q+3]);
}

// combine: thread per (b,d,n), n fastest for coalescing
__global__ void scan_combine(const float* __restrict__ A_log)
{
    int gid = blockIdx.x * blockDim.x + threadIdx.x;
    if (gid >= BSZ * DM * NST) return;
    int n   = gid % NST;
    int rem = gid / NST;
    int d   = rem % DM;
    int b   = rem / DM;

    float Acn = -__expf(A_log[n]);

    float h = 0.f;
    size_t spb = (size_t)b * NCHNK * DM + d;
    size_t hb  = ((size_t)(b * NCHNK) * DM + d) * NST + n;

    float spv = g_sp[spb];
    float he  = g_hend[hb];
#pragma unroll 4
    for (int c = 0; c < NCHNK; c++) {
        float sp_n = 0.f, he_n = 0.f;
        if (c + 1 < NCHNK) {
            sp_n = g_sp[spb + (size_t)(c + 1) * DM];
            he_n = g_hend[hb + (size_t)(c + 1) * DM * NST];
        }
        g_hinit[hb + (size_t)c * DM * NST] = h;
        h = fmaf(__expf(Acn * spv), h, he);
        spv = sp_n; he = he_n;
    }
}

__global__ void scan_passB(const float* __restrict__ A_log, const float* __restrict__ D_param)
{
    int gid = blockIdx.x * blockDim.x + threadIdx.x;
    if (gid >= BSZ * NCHNK * DM) return;
    int d = gid % DM;
    int r = gid / DM;
    int c = r % NCHNK;
    int b = r / NCHNK;

    AConsts a = load_aconsts(A_log);
    float h[NST];
    const float4* hi4 = (const float4*)(g_hinit + ((size_t)(b * NCHNK + c) * DM + d) * NST);
#pragma unroll
    for (int q = 0; q < 4; q++) {
        float4 v = hi4[q];
        h[4*q+0] = v.x; h[4*q+1] = v.y; h[4*q+2] = v.z; h[4*q+3] = v.w;
    }

    float Dp = D_param[d];
    int m0 = b * TLEN + c * CLEN;

    float de = __half2float(g_deltah[(size_t)m0 * DM + d]);
    float xc = __half2float(g_xch[(size_t)m0 * DM + d]);
    float gate = __half2float(g_gateh[(size_t)m0 * DM + d]);

    for (int i = 0; i < CLEN; i++) {
        int m = m0 + i;
        float de_n = 0.f, xc_n = 0.f, gate_n = 0.f;
        if (i + 1 < CLEN) {
            de_n = __half2float(g_deltah[(size_t)(m + 1) * DM + d]);
            xc_n = __half2float(g_xch[(size_t)(m + 1) * DM + d]);
            gate_n = __half2float(g_gateh[(size_t)(m + 1) * DM + d]);
        }
        float dx = de * xc;
        float pw[NST];
        da_powers(a, de, pw);
        const float4* bp = (const float4*)(g_ssm + (size_t)m * SSMW + DTRANK);
        const float4* cp = (const float4*)(g_ssm + (size_t)m * SSMW + DTRANK + NST);
        float y = 0.f;
#pragma unroll
        for (int q = 0; q < 4; q++) {
            float4 bv = bp[q];
            float4 cv = cp[q];
            h[4*q+0] = fmaf(pw[4*q+0], h[4*q+0], dx * bv.x); y = fmaf(h[4*q+0], cv.x, y);
            h[4*q+1] = fmaf(pw[4*q+1], h[4*q+1], dx * bv.y); y = fmaf(h[4*q+1], cv.y, y);
            h[4*q+2] = fmaf(pw[4*q+2], h[4*q+2], dx * bv.z); y = fmaf(h[4*q+2], cv.z, y);
            h[4*q+3] = fmaf(pw[4*q+3], h[4*q+3], dx * bv.w); y = fmaf(h[4*q+3], cv.w, y);
        }
        y = fmaf(xc, Dp, y);
        g_A2h[(size_t)m * 2 * DM + d] = __float2half(y * gate);
        de = de_n; xc = xc_n; gate = gate_n;
    }
}

// ---------------- host launcher ---------------------------------------------
extern "C" void kernel_launch(void* const* d_in, const int* in_sizes, int n_in,
                              void* d_out, int out_size)
{
    const float* x        = (const float*)d_in[0];
    const float* in_w     = (const float*)d_in[1];
    const float* in_b     = (const float*)d_in[2];
    const float* conv_w   = (const float*)d_in[3];
    const float* conv_b   = (const float*)d_in[4];
    const float* xproj_w  = (const float*)d_in[5];
    const float* xproj_b  = (const float*)d_in[6];
    const float* dt_w     = (const float*)d_in[7];
    const float* dt_b     = (const float*)d_in[8];
    const float* A_log    = (const float*)d_in[9];
    const float* D_param  = (const float*)d_in[10];
    const float* out_w    = (const float*)d_in[11];
    const float* out_b    = (const float*)d_in[12];
    const float* skip_w   = (const float*)d_in[13];
    const float* skip_b   = (const float*)d_in[14];
    float* out = (float*)d_out;

    float *p_part;
    __half *p_xch, *p_dth, *p_A2h, *p_Binh, *p_Bxph, *p_Bdth, *p_B2h;
    cudaGetSymbolAddress((void**)&p_part,  g_part);
    cudaGetSymbolAddress((void**)&p_xch,   g_xch);
    cudaGetSymbolAddress((void**)&p_dth,   g_dth);
    cudaGetSymbolAddress((void**)&p_A2h,   g_A2h);
    cudaGetSymbolAddress((void**)&p_Binh,  g_Binh);
    cudaGetSymbolAddress((void**)&p_Bxph,  g_Bxph);
    cudaGetSymbolAddress((void**)&p_Bdth,  g_Bdth);
    cudaGetSymbolAddress((void**)&p_B2h,   g_B2h);

    cudaFuncSetAttribute((const void*)gemm_mma<0,128>, cudaFuncAttributeMaxDynamicSharedMemorySize, GSMEM128);
    cudaFuncSetAttribute((const void*)gemm_mma<5,64>,  cudaFuncAttributeMaxDynamicSharedMemorySize, GSMEM64);
    cudaFuncSetAttribute((const void*)gemm_mma<2,128>, cudaFuncAttributeMaxDynamicSharedMemorySize, GSMEM128);
    cudaFuncSetAttribute((const void*)gemm_mma<4,128>, cudaFuncAttributeMaxDynamicSharedMemorySize, GSMEM128);

    // 0) converts
    {
        const int total = (MTOT * DM + 2 * DM * DM + SSMW * DM + DM * DTRANK + DM * DM) / 4;
        prep_all<<<(total + 255) / 256, 256>>>(x, in_w, xproj_w, dt_w, out_w, skip_w);
    }
    // 1) in_proj -> g_xinh + g_gateh
    {
        dim3 g(2 * DM / 128, MTOT / 128);
        gemm_mma<4,128><<<g, 256, GSMEM128>>>(p_A2h + DM, 2 * DM, p_Binh, DM,
                                              2 * DM, DM / 64, in_b, nullptr,
                                              nullptr, 0, nullptr);
    }
    // 2) conv + silu
    conv_silu<<<(BSZ * (DM / 4) * TCH) / 256, 256>>>(conv_w, conv_b);
    // 3) x_proj split-K4 + reduce
    {
        dim3 g(1, MTOT / 64, XPK);
        gemm_mma<5,64><<<g, 256, GSMEM64>>>(p_xch, DM, p_Bxph, DM,
                                            SSMW, DM / (64 * XPK), nullptr, nullptr,
                                            p_part, SSMW, nullptr);
        xp_reduce<<<(MTOT * SSMW / 4 + 255) / 256, 256>>>(xproj_b);
    }
    // 4) dt_proj -> g_deltah (fp16)
    {
        dim3 g(DM / 128, MTOT / 128);
        gemm_mma<2,128><<<g, 256, GSMEM128>>>(p_dth, DTRANK, p_Bdth, DTRANK,
                                              DM, 1, dt_b, nullptr,
                                              nullptr, 0, nullptr);
    }
    // 5) scan
    scan_passA<<<(BSZ * NCHNK * DM) / 256, 256>>>(A_log);
    scan_combine<<<(BSZ * DM * NST) / 256, 256>>>(A_log);
    scan_passB<<<(BSZ * NCHNK * DM) / 256, 256>>>(A_log, D_param);
    // 6) fused out+skip
    {
        dim3 g(DM / 128, MTOT / 128);
        gemm_mma<0,128><<<g, 256, GSMEM128>>>(p_A2h, 2 * DM, p_B2h, 2 * DM,
                                              DM, 2 * DM / 64, out_b, skip_b,
                                              out, DM, nullptr);
    }
}

// round 16
// speedup vs baseline: 1.1795x; 1.1381x over previous
#include <cuda_runtime.h>
#include <cuda_fp16.h>
#include <math.h>
#include <stdint.h>

// ---------------- problem dims ----------------
#define BSZ    2
#define TLEN   2048
#define DM     1024
#define NST    16
#define DTRANK 64
#define SSMW   96
#define MTOT   (BSZ*TLEN)     // 4096
#define NCHNK  32
#define CLEN   (TLEN/NCHNK)   // 64
#define TCH    128
#define TLCH   (TLEN/TCH)     // 16
#define XPK    4              // x_proj split-K slices

// ---------------- device scratch (no allocations) ----------------
__device__ __half g_xinh[(size_t)MTOT * DM];
__device__ __half g_gateh[(size_t)MTOT * DM];
__device__ __half g_xch [(size_t)MTOT * DM];
__device__ float g_ssm  [(size_t)MTOT * SSMW];
__device__ float g_part [(size_t)XPK * MTOT * SSMW];
__device__ __half g_dth [(size_t)MTOT * DTRANK];
__device__ __half g_deltah[(size_t)MTOT * DM];
__device__ float g_sp   [(size_t)BSZ * NCHNK * DM];
__device__ float g_hend [(size_t)BSZ * NCHNK * DM * NST];   // [b][c][d][n]
__device__ float g_hinit[(size_t)BSZ * NCHNK * DM * NST];   // [b][c][d][n]
__device__ __half g_A2h [(size_t)MTOT * 2 * DM];   // [y | x]
__device__ __half g_Binh[(size_t)2 * DM * DM];
__device__ __half g_Bxph[(size_t)SSMW * DM];
__device__ __half g_Bdth[(size_t)DM * DTRANK];
__device__ __half g_B2h [(size_t)DM * 2 * DM];     // row n: [Wout_n | Wskip_n]

// ---------------- helpers ----------------
__device__ __forceinline__ uint32_t smem_u32(const void* p) {
    uint32_t a;
    asm("{ .reg .u64 t; cvta.to.shared.u64 t, %1; cvt.u32.u64 %0, t; }" : "=r"(a) : "l"(p));
    return a;
}
#define SW128(o) ((o) ^ (((o) >> 3) & 0x70))

__device__ __forceinline__ void ldm_x4(uint32_t* r, uint32_t addr) {
    asm volatile("ldmatrix.sync.aligned.m8n8.x4.shared.b16 {%0,%1,%2,%3}, [%4];"
                 : "=r"(r[0]), "=r"(r[1]), "=r"(r[2]), "=r"(r[3]) : "r"(addr));
}
__device__ __forceinline__ void mma_f16(float* d, const uint32_t* a, const uint32_t* b) {
    asm volatile("mma.sync.aligned.m16n8k16.row.col.f32.f16.f16.f32 "
                 "{%0,%1,%2,%3}, {%4,%5,%6,%7}, {%8,%9}, {%0,%1,%2,%3};"
                 : "+f"(d[0]), "+f"(d[1]), "+f"(d[2]), "+f"(d[3])
                 : "r"(a[0]), "r"(a[1]), "r"(a[2]), "r"(a[3]), "r"(b[0]), "r"(b[1]));
}
__device__ __forceinline__ uint32_t pack2h(float a, float b) {
    __half2 h = __floats2half2_rn(a, b);
    return *(uint32_t*)&h;
}
__device__ __forceinline__ float softplus_f(float v) {
    return (v > 20.f) ? v : __logf(1.f + __expf(v));
}
__device__ __forceinline__ float silu_f(float v) {
    return v / (1.f + __expf(-v));
}

// ---------------- HMMA fp16 GEMM ----------------
// MODE 0: C = acc + bias (+ bias2)      (out+skip fused)
// MODE 2: delta = softplus(acc+bias) -> g_deltah fp16   (dt_proj)
// MODE 4: in_proj: x_in -> g_xinh ; res -> silu -> g_gateh
// MODE 5: x_proj split-K partial
template<int MODE, int BM>
__global__ void __launch_bounds__(256, 2)
gemm_mma(const __half* __restrict__ A, int lda,
         const __half* __restrict__ B, int ldb,
         int Ntot, int KT,
         const float* __restrict__ bias, const float* __restrict__ bias2,
         float* __restrict__ C, int ldc,
         __half* __restrict__ dth)
{
    constexpr int ABYTES = BM * 128;
    constexpr int STG    = ABYTES + 16384;
    constexpr int NT     = (BM == 128) ? 8 : 4;
    constexpr int STAGES = (BM == 128) ? 3 : 4;

    extern __shared__ char smem[];
    const uint32_t sb  = smem_u32(smem);
    const int tid  = threadIdx.x;
    const int wid  = tid >> 5;
    const int lane = tid & 31;
    const int bm   = blockIdx.y * BM;
    const int bn   = blockIdx.x * 128;
    const int kbase = (MODE == 5) ? blockIdx.z * KT * 64 : 0;
    const int wrow = (BM == 128) ? (wid & 3) * 32 : (wid & 1) * 32;
    const int wcol = (BM == 128) ? (wid >> 2) * 64 : (wid >> 1) * 32;

    float acc[2][NT][4];
#pragma unroll
    for (int m = 0; m < 2; m++)
#pragma unroll
        for (int n = 0; n < NT; n++)
#pragma unroll
            for (int v = 0; v < 4; v++) acc[m][n][v] = 0.f;

    auto load_stage = [&](int kt, int s) {
        uint32_t stg = sb + s * STG;
        int koff = kbase + kt * 64;
#pragma unroll
        for (int i = 0; i < BM / 32; i++) {
            int chunk = tid + i * 256;
            int row = chunk >> 3, c16 = chunk & 7;
            uint32_t dst = stg + SW128(row * 128 + c16 * 16);
            const __half* src = A + (size_t)(bm + row) * lda + koff + c16 * 8;
            asm volatile("cp.async.cg.shared.global [%0], [%1], 16;"
                         :: "r"(dst), "l"(src) : "memory");
        }
#pragma unroll
        for (int i = 0; i < 4; i++) {
            int chunk = tid + i * 256;
            int row = chunk >> 3, c16 = chunk & 7;
            uint32_t dst = stg + ABYTES + SW128(row * 128 + c16 * 16);
            int gr = bn + row;
            int sz = 16;
            if (gr >= Ntot) { gr = 0; sz = 0; }
            const __half* src = B + (size_t)gr * ldb + koff + c16 * 8;
            asm volatile("cp.async.cg.shared.global [%0], [%1], 16, %2;"
                         :: "r"(dst), "l"(src), "r"(sz) : "memory");
        }
        asm volatile("cp.async.commit_group;" ::: "memory");
    };

    const int g = lane >> 3, r = lane & 7;
    const uint32_t aoff0 = (wrow + (g & 1) * 8 + r) * 128 + (g >> 1) * 16;
    const uint32_t boff0 = (wcol + (g >> 1) * 8 + r) * 128 + (g & 1) * 16;

    uint32_t afr[2][2][4];
    uint32_t bfr[2][NT][2];

    auto ld_frags = [&](uint32_t stg, int ks, int buf) {
        const int kByte = ks * 32;
#pragma unroll
        for (int m = 0; m < 2; m++)
            ldm_x4(afr[buf][m], stg + SW128(aoff0 + m * 16 * 128 + kByte));
#pragma unroll
        for (int nb = 0; nb < NT / 2; nb++) {
            uint32_t t[4];
            ldm_x4(t, stg + ABYTES + SW128(boff0 + nb * 16 * 128 + kByte));
            bfr[buf][nb * 2][0] = t[0]; bfr[buf][nb * 2][1] = t[1];
            bfr[buf][nb * 2 + 1][0] = t[2]; bfr[buf][nb * 2 + 1][1] = t[3];
        }
    };
    auto do_mma = [&](int buf) {
#pragma unroll
        for (int m = 0; m < 2; m++)
#pragma unroll
            for (int n = 0; n < NT; n++)
                mma_f16(acc[m][n], afr[buf][m], bfr[buf][n]);
    };

    int pf = KT < (STAGES - 1) ? KT : (STAGES - 1);
    for (int s = 0; s < pf; s++) load_stage(s, s);

    for (int kt = 0; kt < KT; kt++) {
        int w = KT - kt - 1;
        if (w > STAGES - 2) w = STAGES - 2;
        if (w == 0)      asm volatile("cp.async.wait_group 0;" ::: "memory");
        else if (w == 1) asm volatile("cp.async.wait_group 1;" ::: "memory");
        else             asm volatile("cp.async.wait_group 2;" ::: "memory");
        __syncthreads();
        if (kt + STAGES - 1 < KT) load_stage(kt + STAGES - 1, (kt + STAGES - 1) % STAGES);

        uint32_t stg = sb + (kt % STAGES) * STG;
        ld_frags(stg, 0, 0);
#pragma unroll
        for (int ks = 0; ks < 4; ks++) {
            int cur = ks & 1;
            if (ks < 3) ld_frags(stg, ks + 1, cur ^ 1);
            do_mma(cur);
        }
    }
    __syncthreads();

    float* epi = (float*)smem;
#pragma unroll
    for (int m = 0; m < 2; m++)
#pragma unroll
        for (int n = 0; n < NT; n++) {
            int row = wrow + m * 16 + (lane >> 2);
            int col = wcol + n * 8 + (lane & 3) * 2;
            epi[row * 128 + col]           = acc[m][n][0];
            epi[row * 128 + col + 1]       = acc[m][n][1];
            epi[(row + 8) * 128 + col]     = acc[m][n][2];
            epi[(row + 8) * 128 + col + 1] = acc[m][n][3];
        }
    __syncthreads();

    const float4* epi4 = (const float4*)epi;
    constexpr int EIT = BM / 8;
    if (MODE == 0) {
#pragma unroll 4
        for (int i = 0; i < EIT; i++) {
            int e = tid + i * 256;
            int row = e >> 5, c4 = e & 31;
            float4 v = epi4[e];
            int n = bn + c4 * 4;
            v.x += bias[n + 0]; v.y += bias[n + 1]; v.z += bias[n + 2]; v.w += bias[n + 3];
            if (bias2) {
                v.x += bias2[n + 0]; v.y += bias2[n + 1]; v.z += bias2[n + 2]; v.w += bias2[n + 3];
            }
            *(float4*)(C + (size_t)(bm + row) * ldc + n) = v;
        }
    } else if (MODE == 4) {
#pragma unroll 4
        for (int i = 0; i < EIT; i++) {
            int e = tid + i * 256;
            int row = e >> 5, c4 = e & 31;
            float4 v = epi4[e];
            int n = bn + c4 * 4;
            v.x += bias[n + 0]; v.y += bias[n + 1]; v.z += bias[n + 2]; v.w += bias[n + 3];
            if (bn < DM) {
                uint2 pk = make_uint2(pack2h(v.x, v.y), pack2h(v.z, v.w));
                *(uint2*)(g_xinh + (size_t)(bm + row) * DM + n) = pk;
            } else {
                uint2 pk = make_uint2(pack2h(silu_f(v.x), silu_f(v.y)),
                                      pack2h(silu_f(v.z), silu_f(v.w)));
                *(uint2*)(g_gateh + (size_t)(bm + row) * DM + (n - DM)) = pk;
            }
        }
    } else if (MODE == 2) {
#pragma unroll 4
        for (int i = 0; i < EIT; i++) {
            int e = tid + i * 256;
            int row = e >> 5, c4 = e & 31;
            float4 v = epi4[e];
            int n = bn + c4 * 4;
            v.x += bias[n + 0]; v.y += bias[n + 1]; v.z += bias[n + 2]; v.w += bias[n + 3];
            uint2 pk = make_uint2(pack2h(softplus_f(v.x), softplus_f(v.y)),
                                  pack2h(softplus_f(v.z), softplus_f(v.w)));
            *(uint2*)(g_deltah + (size_t)(bm + row) * DM + n) = pk;
        }
    } else { // MODE 5
        float* part = C + (size_t)blockIdx.z * MTOT * SSMW;
        for (int i = 0; i < EIT; i++) {
            int e = tid + i * 256;
            int row = e >> 5, c4 = e & 31;
            if (c4 >= 24) continue;
            float4 v = epi4[e];
            *(float4*)(part + (size_t)(bm + row) * SSMW + c4 * 4) = v;
        }
    }
}

#define GSMEM128 (3 * (128 * 128 + 16384))   // 98304
#define GSMEM64  (4 * (64 * 128 + 16384))    // 98304

// ---------------- x_proj split-K reduce (float4) ----------------
__global__ void xp_reduce(const float* __restrict__ xproj_b)
{
    int i4 = blockIdx.x * 256 + threadIdx.x;
    if (i4 >= MTOT * SSMW / 4) return;
    int i = i4 * 4;
    int m = i / SSMW, c = i % SSMW;
    float4 s = *(const float4*)(xproj_b + c);
#pragma unroll
    for (int z = 0; z < XPK; z++) {
        float4 p = *(const float4*)(g_part + (size_t)z * MTOT * SSMW + i);
        s.x += p.x; s.y += p.y; s.z += p.z; s.w += p.w;
    }
    *(float4*)(g_ssm + i) = s;
    if (c < DTRANK) {
        uint2 pk = make_uint2(pack2h(s.x, s.y), pack2h(s.z, s.w));
        *(uint2*)(g_dth + (size_t)m * DTRANK + c) = pk;
    }
}

// ---------------- fused converts (float4 vectorized) ----------------
__global__ void prep_all(const float* __restrict__ x, const float* __restrict__ in_w,
                         const float* __restrict__ xproj_w, const float* __restrict__ dt_w,
                         const float* __restrict__ out_w, const float* __restrict__ skip_w)
{
    const int NX  = MTOT * DM / 4;
    const int NIN = 2 * DM * DM / 4;
    const int NXP = SSMW * DM / 4;
    const int NDT = DM * DTRANK / 4;
    const int NO  = DM * DM / 4;
    int i = blockIdx.x * 256 + threadIdx.x;
    if (i < NX) {
        int e = i * 4;
        int m = e >> 10, c = e & 1023;
        float4 v = *(const float4*)(x + e);
        *(uint2*)(g_A2h + (size_t)m * 2048 + 1024 + c) =
            make_uint2(pack2h(v.x, v.y), pack2h(v.z, v.w));
        return;
    }
    i -= NX;
    if (i < NIN) {
        float4 v = *(const float4*)(in_w + i * 4);
        *(uint2*)(g_Binh + i * 4) = make_uint2(pack2h(v.x, v.y), pack2h(v.z, v.w));
        return;
    }
    i -= NIN;
    if (i < NXP) {
        float4 v = *(const float4*)(xproj_w + i * 4);
        *(uint2*)(g_Bxph + i * 4) = make_uint2(pack2h(v.x, v.y), pack2h(v.z, v.w));
        return;
    }
    i -= NXP;
    if (i < NDT) {
        float4 v = *(const float4*)(dt_w + i * 4);
        *(uint2*)(g_Bdth + i * 4) = make_uint2(pack2h(v.x, v.y), pack2h(v.z, v.w));
        return;
    }
    i -= NDT;
    if (i < NO) {
        int e = i * 4;
        int m = e >> 10, c = e & 1023;
        size_t o = (size_t)m * 2048;
        float4 v = *(const float4*)(out_w + e);
        *(uint2*)(g_B2h + o + c) = make_uint2(pack2h(v.x, v.y), pack2h(v.z, v.w));
        v = *(const float4*)(skip_w + e);
        *(uint2*)(g_B2h + o + 1024 + c) = make_uint2(pack2h(v.x, v.y), pack2h(v.z, v.w));
    }
}

// ---------------- depthwise causal conv (k=4) + silu, 4 channels/thread -----
__global__ void conv_silu(const float* __restrict__ cw, const float* __restrict__ cb)
{
    int gid = blockIdx.x * blockDim.x + threadIdx.x;
    if (gid >= BSZ * (DM / 4) * TCH) return;
    int d4 = gid % (DM / 4);
    int r  = gid / (DM / 4);
    int tc = r % TCH;
    int b  = r / TCH;
    int d  = d4 * 4;

    float w[4][4], bs[4];
#pragma unroll
    for (int j = 0; j < 4; j++) {
        float4 wv = *(const float4*)(cw + (d + j) * 4);
        w[j][0] = wv.x; w[j][1] = wv.y; w[j][2] = wv.z; w[j][3] = wv.w;
        bs[j] = cb[d + j];
    }
    int t0 = tc * TLCH;

    const uint2* xin = (const uint2*)g_xinh + (size_t)b * TLEN * (DM / 4) + d4;
    uint2* xout = (uint2*)g_xch + (size_t)b * TLEN * (DM / 4) + d4;

    auto unpk = [](uint2 u, float* f) {
        __half2 lo = *(__half2*)&u.x, hi = *(__half2*)&u.y;
        float2 a = __half22float2(lo), c = __half22float2(hi);
        f[0] = a.x; f[1] = a.y; f[2] = c.x; f[3] = c.y;
    };

    float hist[3][4];
#pragma unroll
    for (int k = 0; k < 3; k++)
#pragma unroll
        for (int j = 0; j < 4; j++) hist[k][j] = 0.f;
    if (t0 - 3 >= 0) unpk(xin[(size_t)(t0 - 3) * (DM / 4)], hist[0]);
    if (t0 - 2 >= 0) unpk(xin[(size_t)(t0 - 2) * (DM / 4)], hist[1]);
    if (t0 - 1 >= 0) unpk(xin[(size_t)(t0 - 1) * (DM / 4)], hist[2]);

#pragma unroll 4
    for (int i = 0; i < TLCH; i++) {
        int t = t0 + i;
        float x0[4];
        unpk(xin[(size_t)t * (DM / 4)], x0);
        float s[4];
#pragma unroll
        for (int j = 0; j < 4; j++) {
            float a = bs[j];
            a = fmaf(w[j][0], hist[0][j], a);
            a = fmaf(w[j][1], hist[1][j], a);
            a = fmaf(w[j][2], hist[2][j], a);
            a = fmaf(w[j][3], x0[j], a);
            s[j] = silu_f(a);
        }
        xout[(size_t)t * (DM / 4)] = make_uint2(pack2h(s[0], s[1]), pack2h(s[2], s[3]));
#pragma unroll
        for (int j = 0; j < 4; j++) {
            hist[0][j] = hist[1][j]; hist[1][j] = hist[2][j]; hist[2][j] = x0[j];
        }
    }
}

// ---------------- dA powers ----------------
struct AConsts {
    float Ac[NST];
    float Ac0;
    bool  geom;
};
__device__ __forceinline__ AConsts load_aconsts(const float* A_log) {
    AConsts a;
#pragma unroll
    for (int n = 0; n < NST; n++) a.Ac[n] = -__expf(A_log[n]);
    a.Ac0 = a.Ac[0];
    a.geom = true;
#pragma unroll
    for (int n = 0; n < NST; n++)
        a.geom = a.geom && (fabsf(a.Ac[n] - (float)(n + 1) * a.Ac0) <= 1e-5f * fabsf(a.Ac[n]));
    return a;
}
__device__ __forceinline__ void da_powers(const AConsts& a, float de, float* pw) {
    if (a.geom) {
        float r = __expf(a.Ac0 * de);
        pw[0] = r;
        pw[1] = pw[0] * pw[0];  pw[2] = pw[1] * pw[0];  pw[3] = pw[1] * pw[1];
        pw[4] = pw[2] * pw[1];  pw[5] = pw[2] * pw[2];  pw[6] = pw[3] * pw[2];
        pw[7] = pw[3] * pw[3];  pw[8] = pw[4] * pw[3];  pw[9] = pw[4] * pw[4];
        pw[10] = pw[5] * pw[4]; pw[11] = pw[5] * pw[5]; pw[12] = pw[6] * pw[5];
        pw[13] = pw[6] * pw[6]; pw[14] = pw[7] * pw[6]; pw[15] = pw[7] * pw[7];
    } else {
#pragma unroll
        for (int n = 0; n < NST; n++) pw[n] = __expf(a.Ac[n] * de);
    }
}

// ---------------- chunked selective scan (smem-staged B/C) ------------------
// block = 256 consecutive d of one (b,c); B/C rows identical across the block.
__global__ void scan_passA(const float* __restrict__ A_log)
{
    __shared__ float s_b[CLEN * 16];          // B rows: CLEN x 16
    int gid = blockIdx.x * blockDim.x + threadIdx.x;
    int tid = threadIdx.x;
    int d = gid % DM;
    int r = gid / DM;
    int c = r % NCHNK;
    int b = r / NCHNK;
    int m0 = b * TLEN + c * CLEN;

    // cooperative stage: 256 float4 = CLEN*16 floats
    {
        int t = tid >> 2, q = tid & 3;
        ((float4*)s_b)[tid] = *(const float4*)(g_ssm + (size_t)(m0 + t) * SSMW + DTRANK + q * 4);
    }
    __syncthreads();

    AConsts a = load_aconsts(A_log);
    float h[NST];
#pragma unroll
    for (int n = 0; n < NST; n++) h[n] = 0.f;
    float sp = 0.f;

    float de = __half2float(g_deltah[(size_t)m0 * DM + d]);
    float xc = __half2float(g_xch[(size_t)m0 * DM + d]);

    for (int i = 0; i < CLEN; i++) {
        int m = m0 + i;
        float de_n = 0.f, xc_n = 0.f;
        if (i + 1 < CLEN) {
            de_n = __half2float(g_deltah[(size_t)(m + 1) * DM + d]);
            xc_n = __half2float(g_xch[(size_t)(m + 1) * DM + d]);
        }
        float dx = de * xc;
        sp += de;
        float pw[NST];
        da_powers(a, de, pw);
        const float4* bp = (const float4*)(s_b + i * 16);
#pragma unroll
        for (int q = 0; q < 4; q++) {
            float4 bv = bp[q];
            h[4*q+0] = fmaf(pw[4*q+0], h[4*q+0], dx * bv.x);
            h[4*q+1] = fmaf(pw[4*q+1], h[4*q+1], dx * bv.y);
            h[4*q+2] = fmaf(pw[4*q+2], h[4*q+2], dx * bv.z);
            h[4*q+3] = fmaf(pw[4*q+3], h[4*q+3], dx * bv.w);
        }
        de = de_n; xc = xc_n;
    }
    g_sp[(size_t)(b * NCHNK + c) * DM + d] = sp;
    float4* he = (float4*)(g_hend + ((size_t)(b * NCHNK + c) * DM + d) * NST);
#pragma unroll
    for (int q = 0; q < 4; q++)
        he[q] = make_float4(h[4*q+0], h[4*q+1], h[4*q+2], h[4*q+3]);
}

// combine: thread per (b,d,n), n fastest for coalescing
__global__ void scan_combine(const float* __restrict__ A_log)
{
    int gid = blockIdx.x * blockDim.x + threadIdx.x;
    if (gid >= BSZ * DM * NST) return;
    int n   = gid % NST;
    int rem = gid / NST;
    int d   = rem % DM;
    int b   = rem / DM;

    float Acn = -__expf(A_log[n]);

    float h = 0.f;
    size_t spb = (size_t)b * NCHNK * DM + d;
    size_t hb  = ((size_t)(b * NCHNK) * DM + d) * NST + n;

    float spv = g_sp[spb];
    float he  = g_hend[hb];
#pragma unroll 4
    for (int c = 0; c < NCHNK; c++) {
        float sp_n = 0.f, he_n = 0.f;
        if (c + 1 < NCHNK) {
            sp_n = g_sp[spb + (size_t)(c + 1) * DM];
            he_n = g_hend[hb + (size_t)(c + 1) * DM * NST];
        }
        g_hinit[hb + (size_t)c * DM * NST] = h;
        h = fmaf(__expf(Acn * spv), h, he);
        spv = sp_n; he = he_n;
    }
}

__global__ void scan_passB(const float* __restrict__ A_log, const float* __restrict__ D_param)
{
    __shared__ float s_bc[CLEN * 32];         // B|C rows: CLEN x 32
    int gid = blockIdx.x * blockDim.x + threadIdx.x;
    int tid = threadIdx.x;
    int d = gid % DM;
    int r = gid / DM;
    int c = r % NCHNK;
    int b = r / NCHNK;
    int m0 = b * TLEN + c * CLEN;

    // cooperative stage: 512 float4 = CLEN*32 floats (2 per thread)
#pragma unroll
    for (int k = 0; k < 2; k++) {
        int chunk = tid + k * 256;
        int t = chunk >> 3, q = chunk & 7;
        ((float4*)s_bc)[chunk] = *(const float4*)(g_ssm + (size_t)(m0 + t) * SSMW + DTRANK + q * 4);
    }
    __syncthreads();

    AConsts a = load_aconsts(A_log);
    float h[NST];
    const float4* hi4 = (const float4*)(g_hinit + ((size_t)(b * NCHNK + c) * DM + d) * NST);
#pragma unroll
    for (int q = 0; q < 4; q++) {
        float4 v = hi4[q];
        h[4*q+0] = v.x; h[4*q+1] = v.y; h[4*q+2] = v.z; h[4*q+3] = v.w;
    }

    float Dp = D_param[d];

    float de = __half2float(g_deltah[(size_t)m0 * DM + d]);
    float xc = __half2float(g_xch[(size_t)m0 * DM + d]);
    float gate = __half2float(g_gateh[(size_t)m0 * DM + d]);

    for (int i = 0; i < CLEN; i++) {
        int m = m0 + i;
        float de_n = 0.f, xc_n = 0.f, gate_n = 0.f;
        if (i + 1 < CLEN) {
            de_n = __half2float(g_deltah[(size_t)(m + 1) * DM + d]);
            xc_n = __half2float(g_xch[(size_t)(m + 1) * DM + d]);
            gate_n = __half2float(g_gateh[(size_t)(m + 1) * DM + d]);
        }
        float dx = de * xc;
        float pw[NST];
        da_powers(a, de, pw);
        const float4* bp = (const float4*)(s_bc + i * 32);
        const float4* cp = bp + 4;
        float y = 0.f;
#pragma unroll
        for (int q = 0; q < 4; q++) {
            float4 bv = bp[q];
            float4 cv = cp[q];
            h[4*q+0] = fmaf(pw[4*q+0], h[4*q+0], dx * bv.x); y = fmaf(h[4*q+0], cv.x, y);
            h[4*q+1] = fmaf(pw[4*q+1], h[4*q+1], dx * bv.y); y = fmaf(h[4*q+1], cv.y, y);
            h[4*q+2] = fmaf(pw[4*q+2], h[4*q+2], dx * bv.z); y = fmaf(h[4*q+2], cv.z, y);
            h[4*q+3] = fmaf(pw[4*q+3], h[4*q+3], dx * bv.w); y = fmaf(h[4*q+3], cv.w, y);
        }
        y = fmaf(xc, Dp, y);
        g_A2h[(size_t)m * 2 * DM + d] = __float2half(y * gate);
        de = de_n; xc = xc_n; gate = gate_n;
    }
}

// ---------------- host launcher ---------------------------------------------
extern "C" void kernel_launch(void* const* d_in, const int* in_sizes, int n_in,
                              void* d_out, int out_size)
{
    const float* x        = (const float*)d_in[0];
    const float* in_w     = (const float*)d_in[1];
    const float* in_b     = (const float*)d_in[2];
    const float* conv_w   = (const float*)d_in[3];
    const float* conv_b   = (const float*)d_in[4];
    const float* xproj_w  = (const float*)d_in[5];
    const float* xproj_b  = (const float*)d_in[6];
    const float* dt_w     = (const float*)d_in[7];
    const float* dt_b     = (const float*)d_in[8];
    const float* A_log    = (const float*)d_in[9];
    const float* D_param  = (const float*)d_in[10];
    const float* out_w    = (const float*)d_in[11];
    const float* out_b    = (const float*)d_in[12];
    const float* skip_w   = (const float*)d_in[13];
    const float* skip_b   = (const float*)d_in[14];
    float* out = (float*)d_out;

    float *p_part;
    __half *p_xch, *p_dth, *p_A2h, *p_Binh, *p_Bxph, *p_Bdth, *p_B2h;
    cudaGetSymbolAddress((void**)&p_part,  g_part);
    cudaGetSymbolAddress((void**)&p_xch,   g_xch);
    cudaGetSymbolAddress((void**)&p_dth,   g_dth);
    cudaGetSymbolAddress((void**)&p_A2h,   g_A2h);
    cudaGetSymbolAddress((void**)&p_Binh,  g_Binh);
    cudaGetSymbolAddress((void**)&p_Bxph,  g_Bxph);
    cudaGetSymbolAddress((void**)&p_Bdth,  g_Bdth);
    cudaGetSymbolAddress((void**)&p_B2h,   g_B2h);

    cudaFuncSetAttribute((const void*)gemm_mma<0,128>, cudaFuncAttributeMaxDynamicSharedMemorySize, GSMEM128);
    cudaFuncSetAttribute((const void*)gemm_mma<5,64>,  cudaFuncAttributeMaxDynamicSharedMemorySize, GSMEM64);
    cudaFuncSetAttribute((const void*)gemm_mma<2,128>, cudaFuncAttributeMaxDynamicSharedMemorySize, GSMEM128);
    cudaFuncSetAttribute((const void*)gemm_mma<4,128>, cudaFuncAttributeMaxDynamicSharedMemorySize, GSMEM128);

    // 0) converts
    {
        const int total = (MTOT * DM + 2 * DM * DM + SSMW * DM + DM * DTRANK + DM * DM) / 4;
        prep_all<<<(total + 255) / 256, 256>>>(x, in_w, xproj_w, dt_w, out_w, skip_w);
    }
    // 1) in_proj -> g_xinh + g_gateh
    {
        dim3 g(2 * DM / 128, MTOT / 128);
        gemm_mma<4,128><<<g, 256, GSMEM128>>>(p_A2h + DM, 2 * DM, p_Binh, DM,
                                              2 * DM, DM / 64, in_b, nullptr,
                                              nullptr, 0, nullptr);
    }
    // 2) conv + silu
    conv_silu<<<(BSZ * (DM / 4) * TCH) / 256, 256>>>(conv_w, conv_b);
    // 3) x_proj split-K4 + reduce
    {
        dim3 g(1, MTOT / 64, XPK);
        gemm_mma<5,64><<<g, 256, GSMEM64>>>(p_xch, DM, p_Bxph, DM,
                                            SSMW, DM / (64 * XPK), nullptr, nullptr,
                                            p_part, SSMW, nullptr);
        xp_reduce<<<(MTOT * SSMW / 4 + 255) / 256, 256>>>(xproj_b);
    }
    // 4) dt_proj -> g_deltah (fp16)
    {
        dim3 g(DM / 128, MTOT / 128);
        gemm_mma<2,128><<<g, 256, GSMEM128>>>(p_dth, DTRANK, p_Bdth, DTRANK,
                                              DM, 1, dt_b, nullptr,
                                              nullptr, 0, nullptr);
    }
    // 5) scan
    scan_passA<<<(BSZ * NCHNK * DM) / 256, 256>>>(A_log);
    scan_combine<<<(BSZ * DM * NST) / 256, 256>>>(A_log);
    scan_passB<<<(BSZ * NCHNK * DM) / 256, 256>>>(A_log, D_param);
    // 6) fused out+skip
    {
        dim3 g(DM / 128, MTOT / 128);
        gemm_mma<0,128><<<g, 256, GSMEM128>>>(p_A2h, 2 * DM, p_B2h, 2 * DM,
                                              DM, 2 * DM / 64, out_b, skip_b,
                                              out, DM, nullptr);
    }
}